// round 10
// baseline (speedup 1.0000x reference)
#include <cuda_runtime.h>
#include <cuda_bf16.h>
#include <stdint.h>

#define B_DIM 64
#define S_DIM 512
#define H_DIM 1024
#define L_DIM 512
#define NEG_INF_F (-1e9f)
#define NCTA 296        // 2 per SM on 148 SMs (all co-resident on 148 or 152)

// ---------------------------------------------------------------------------
// Scratch (module-load allocations, allowed)
// ---------------------------------------------------------------------------
__device__ float         g_scores[(size_t)B_DIM * L_DIM * S_DIM];
__device__ __nv_bfloat16 g_Xh[(size_t)B_DIM * S_DIM * H_DIM];      // compacted
__device__ __nv_bfloat16 g_Xl[(size_t)B_DIM * S_DIM * H_DIM];
__device__ __nv_bfloat16 g_Wh[(size_t)L_DIM * H_DIM];
__device__ __nv_bfloat16 g_Wl[(size_t)L_DIM * H_DIM];
__device__ __nv_bfloat16 g_Ph[(size_t)B_DIM * L_DIM * S_DIM];      // compacted K
__device__ __nv_bfloat16 g_Pl[(size_t)B_DIM * L_DIM * S_DIM];
__device__ int g_idx[B_DIM * S_DIM];
__device__ int g_cnt[B_DIM];
__device__ int g_npad[B_DIM];          // cnt rounded up to 64

// ---------------------------------------------------------------------------
// Helpers
// ---------------------------------------------------------------------------
__device__ __forceinline__ uint32_t smem_u32(const void* p) {
    uint32_t a;
    asm("{ .reg .u64 t; cvta.to.shared.u64 t, %1; cvt.u32.u64 %0, t; }" : "=r"(a) : "l"(p));
    return a;
}

#define CP_ASYNC16(dst, src) \
    asm volatile("cp.async.cg.shared.global [%0], [%1], 16;" :: "r"(dst), "l"(src))
#define CP_COMMIT()  asm volatile("cp.async.commit_group;" ::: "memory")
#define CP_WAIT1()   asm volatile("cp.async.wait_group 1;" ::: "memory")

#define LDSM_X4(r0, r1, r2, r3, a) \
    asm volatile("ldmatrix.sync.aligned.m8n8.x4.shared.b16 {%0,%1,%2,%3}, [%4];" \
        : "=r"(r0), "=r"(r1), "=r"(r2), "=r"(r3) : "r"(a))
#define LDSM_X4T(r0, r1, r2, r3, a) \
    asm volatile("ldmatrix.sync.aligned.m8n8.x4.trans.shared.b16 {%0,%1,%2,%3}, [%4];" \
        : "=r"(r0), "=r"(r1), "=r"(r2), "=r"(r3) : "r"(a))

#define MMA_BF16(d, a0, a1, a2, a3, b0, b1) \
    asm volatile("mma.sync.aligned.m16n8k16.row.col.f32.bf16.bf16.f32 " \
        "{%0,%1,%2,%3},{%4,%5,%6,%7},{%8,%9},{%0,%1,%2,%3};" \
        : "+f"((d)[0]), "+f"((d)[1]), "+f"((d)[2]), "+f"((d)[3]) \
        : "r"(a0), "r"(a1), "r"(a2), "r"(a3), "r"(b0), "r"(b1))

#define SWZ128(o) ((o) ^ (((o) >> 3) & 0x70))

__device__ __forceinline__ void split2(float v, __nv_bfloat16& h, __nv_bfloat16& l) {
    h = __float2bfloat16(v);
    l = __float2bfloat16(v - __bfloat162float(h));
}

// ---------------------------------------------------------------------------
// Mask compaction: one block of 512 threads per batch.
// ---------------------------------------------------------------------------
__global__ void __launch_bounds__(512) compact_mask(const int* __restrict__ mask) {
    const int b = blockIdx.x, tid = threadIdx.x;
    const int lane = tid & 31, w = tid >> 5;
    const int m = (mask[(size_t)b * S_DIM + tid] != 0);
    const unsigned bal = __ballot_sync(0xffffffffu, m);

    __shared__ int ws[16], woff[16];
    if (lane == 0) ws[w] = __popc(bal);
    __syncthreads();
    if (tid == 0) {
        int s = 0;
        #pragma unroll
        for (int i = 0; i < 16; ++i) { woff[i] = s; s += ws[i]; }
        g_cnt[b]  = s;
        int np = ((s + 63) >> 6) << 6;
        g_npad[b] = (np < 64) ? 64 : np;
    }
    __syncthreads();
    if (m) {
        int pos = woff[w] + __popc(bal & ((1u << lane) - 1u));
        g_idx[b * S_DIM + pos] = tid;
    }
}

// ---------------------------------------------------------------------------
// Gather + split-convert X. Rows j >= npad are never read by either GEMM.
// ---------------------------------------------------------------------------
__global__ void __launch_bounds__(256) gather_convert_X(const float* __restrict__ X) {
    const int j = blockIdx.x, b = blockIdx.y;
    if (j >= g_npad[b]) return;
    const int cnt = g_cnt[b];
    const size_t o = ((size_t)b * S_DIM + j) * H_DIM + threadIdx.x * 4;
    if (j < cnt) {
        const int s = g_idx[b * S_DIM + j];
        float4 v = *reinterpret_cast<const float4*>(X + ((size_t)b * S_DIM + s) * H_DIM + threadIdx.x * 4);
        __nv_bfloat16 h0, l0, h1, l1, h2, l2, h3, l3;
        split2(v.x, h0, l0); split2(v.y, h1, l1); split2(v.z, h2, l2); split2(v.w, h3, l3);
        *reinterpret_cast<__nv_bfloat162*>(g_Xh + o)     = __nv_bfloat162{h0, h1};
        *reinterpret_cast<__nv_bfloat162*>(g_Xh + o + 2) = __nv_bfloat162{h2, h3};
        *reinterpret_cast<__nv_bfloat162*>(g_Xl + o)     = __nv_bfloat162{l0, l1};
        *reinterpret_cast<__nv_bfloat162*>(g_Xl + o + 2) = __nv_bfloat162{l2, l3};
    } else {
        *reinterpret_cast<uint2*>(g_Xh + o) = make_uint2(0, 0);
        *reinterpret_cast<uint2*>(g_Xl + o) = make_uint2(0, 0);
    }
}

__global__ void convert_W(const float* __restrict__ W) {
    size_t i = ((size_t)blockIdx.x * 256 + threadIdx.x) * 4;
    float4 v = *reinterpret_cast<const float4*>(W + i);
    __nv_bfloat16 h0, l0, h1, l1, h2, l2, h3, l3;
    split2(v.x, h0, l0); split2(v.y, h1, l1); split2(v.z, h2, l2); split2(v.w, h3, l3);
    *reinterpret_cast<__nv_bfloat162*>(g_Wh + i)     = __nv_bfloat162{h0, h1};
    *reinterpret_cast<__nv_bfloat162*>(g_Wh + i + 2) = __nv_bfloat162{h2, h3};
    *reinterpret_cast<__nv_bfloat162*>(g_Wl + i)     = __nv_bfloat162{l0, l1};
    *reinterpret_cast<__nv_bfloat162*>(g_Wl + i + 2) = __nv_bfloat162{l2, l3};
}

// ---------------------------------------------------------------------------
// Persistent bf16x3 split GEMM via mma.sync. CTA tile 128(M) x 64(N),
// K-chunk 64, 8 warps (4M x 2N), warp tile 32x32. 2-stage cp.async pipeline,
// 2 CTAs/SM, NCTA persistent CTAs; load stream runs one chunk-unit ahead of
// compute ACROSS tile boundaries (prologue paid once per CTA, epilogues
// overlap next tile's loads).
//   G1: tiles (b, y<4, x<8), live if x*64 < npad[b]; B = Xc K-major; nk=16
//   G2: tiles (b, y<4, x<16), all live; B = Xc row-major; nk = npad[b]/64
// ---------------------------------------------------------------------------
#define STAGE_BYTES 49152
#define GEMM_SMEM   (2 * STAGE_BYTES)
#define NT1 (B_DIM * 32)   // 2048
#define NT2 (B_DIM * 64)   // 4096

template <bool G1>
__device__ __forceinline__ bool tile_live(int t) {
    if (!G1) return true;
    return ((t & 7) << 6) < g_npad[t >> 5];
}

template <bool G1>
__device__ __forceinline__ int tile_nk(int t) {
    return G1 ? (H_DIM / 64) : (g_npad[t >> 6] >> 6);
}

// advance (t, c) to the next chunk-unit; returns false when exhausted
template <bool G1>
__device__ __forceinline__ bool adv(int& t, int& c, int& nk, int NT) {
    if (c + 1 < nk) { c++; return true; }
    t += NCTA;
    if (G1) { while (t < NT && !tile_live<true>(t)) t += NCTA; }
    if (t >= NT) return false;
    nk = tile_nk<G1>(t);
    c = 0;
    return true;
}

template <bool G1>
__global__ void __launch_bounds__(256, 2) gemm_persist(
    const __nv_bfloat16* __restrict__ Ah, const __nv_bfloat16* __restrict__ Al,
    const __nv_bfloat16* __restrict__ Bh, const __nv_bfloat16* __restrict__ Bl,
    float* __restrict__ D,
    int lda, int ldb, int ldd,
    size_t strideA, size_t strideB, size_t strideD, int NT)
{
    extern __shared__ char smem[];
    const uint32_t sb = smem_u32(smem);
    const int tid = threadIdx.x;
    const int wid = tid >> 5, lane = tid & 31;
    const int warp_m = wid & 3, warp_n = wid >> 2;

    // first live tile for this CTA
    int t0 = blockIdx.x;
    if (G1) { while (t0 < NT && !tile_live<true>(t0)) t0 += NCTA; }
    if (t0 >= NT) return;
    const int nk0 = tile_nk<G1>(t0);

    // load iterator / compute iterator
    int tl = t0, cl = 0, nkl = nk0;
    int tc = t0, cc = 0, nkc = nk0;

    float acc[2][4][4];

    auto load_unit = [&](int t, int c, int st) {
        int b, m0, n0;
        if (G1) { b = t >> 5; m0 = ((t >> 3) & 3) << 7; n0 = (t & 7) << 6; }
        else    { b = t >> 6; m0 = ((t >> 4) & 3) << 7; n0 = (t & 15) << 6; }
        const __nv_bfloat16* tAh = Ah + (size_t)b * strideA + (size_t)m0 * lda;
        const __nv_bfloat16* tAl = Al + (size_t)b * strideA + (size_t)m0 * lda;
        const __nv_bfloat16* pBh = Bh + (size_t)b * strideB;
        const __nv_bfloat16* pBl = Bl + (size_t)b * strideB;
        const uint32_t base = sb + st * STAGE_BYTES;
        #pragma unroll
        for (int i = 0; i < 4; ++i) {
            int idx = i * 256 + tid;
            int row = idx >> 3, sl = idx & 7;
            uint32_t doff = SWZ128(row * 128 + sl * 16);
            CP_ASYNC16(base + doff,         tAh + (size_t)row * lda + c * 64 + sl * 8);
            CP_ASYNC16(base + 16384 + doff, tAl + (size_t)row * lda + c * 64 + sl * 8);
        }
        #pragma unroll
        for (int i = 0; i < 2; ++i) {
            int idx = i * 256 + tid;
            int row = idx >> 3, sl = idx & 7;
            uint32_t doff = SWZ128(row * 128 + sl * 16);
            if (G1) {
                CP_ASYNC16(base + 32768 + doff, pBh + (size_t)(n0 + row) * ldb + c * 64 + sl * 8);
                CP_ASYNC16(base + 40960 + doff, pBl + (size_t)(n0 + row) * ldb + c * 64 + sl * 8);
            } else {
                CP_ASYNC16(base + 32768 + doff, pBh + (size_t)(c * 64 + row) * ldb + n0 + sl * 8);
                CP_ASYNC16(base + 40960 + doff, pBl + (size_t)(c * 64 + row) * ldb + n0 + sl * 8);
            }
        }
        CP_COMMIT();
    };

    auto compute_unit = [&](int st) {
        const uint32_t base = sb + st * STAGE_BYTES;
        const uint32_t sAh = base, sAl = base + 16384;
        const uint32_t sBh = base + 32768, sBl = base + 40960;
        #pragma unroll
        for (int ks = 0; ks < 4; ++ks) {
            uint32_t ah[2][4], al[2][4];
            #pragma unroll
            for (int mt = 0; mt < 2; ++mt) {
                int row = warp_m * 32 + mt * 16 + (lane & 15);
                uint32_t off = SWZ128(row * 128 + ks * 32 + ((lane >> 4) << 4));
                LDSM_X4(ah[mt][0], ah[mt][1], ah[mt][2], ah[mt][3], sAh + off);
                LDSM_X4(al[mt][0], al[mt][1], al[mt][2], al[mt][3], sAl + off);
            }
            uint32_t bh[4][2], bl[4][2];
            #pragma unroll
            for (int nt2 = 0; nt2 < 2; ++nt2) {
                if (G1) {
                    int row = warp_n * 32 + nt2 * 16 + ((lane >> 4) << 3) + (lane & 7);
                    uint32_t off = SWZ128(row * 128 + ks * 32 + (((lane >> 3) & 1) << 4));
                    LDSM_X4(bh[2 * nt2][0], bh[2 * nt2][1], bh[2 * nt2 + 1][0], bh[2 * nt2 + 1][1], sBh + off);
                    LDSM_X4(bl[2 * nt2][0], bl[2 * nt2][1], bl[2 * nt2 + 1][0], bl[2 * nt2 + 1][1], sBl + off);
                } else {
                    int krow = ks * 16 + (((lane >> 3) & 1) << 3) + (lane & 7);
                    int col  = warp_n * 32 + nt2 * 16 + ((lane >> 4) << 3);
                    uint32_t off = SWZ128(krow * 128 + col * 2);
                    LDSM_X4T(bh[2 * nt2][0], bh[2 * nt2][1], bh[2 * nt2 + 1][0], bh[2 * nt2 + 1][1], sBh + off);
                    LDSM_X4T(bl[2 * nt2][0], bl[2 * nt2][1], bl[2 * nt2 + 1][0], bl[2 * nt2 + 1][1], sBl + off);
                }
            }
            #pragma unroll
            for (int mt = 0; mt < 2; ++mt)
                #pragma unroll
                for (int nt = 0; nt < 4; ++nt) {
                    MMA_BF16(acc[mt][nt], ah[mt][0], ah[mt][1], ah[mt][2], ah[mt][3], bh[nt][0], bh[nt][1]);
                    MMA_BF16(acc[mt][nt], ah[mt][0], ah[mt][1], ah[mt][2], ah[mt][3], bl[nt][0], bl[nt][1]);
                    MMA_BF16(acc[mt][nt], al[mt][0], al[mt][1], al[mt][2], al[mt][3], bh[nt][0], bh[nt][1]);
                }
        }
    };

    auto epilogue = [&](int t) {
        int b, m0, n0;
        if (G1) { b = t >> 5; m0 = ((t >> 3) & 3) << 7; n0 = (t & 7) << 6; }
        else    { b = t >> 6; m0 = ((t >> 4) & 3) << 7; n0 = (t & 15) << 6; }
        float* Db = D + (size_t)b * strideD;
        #pragma unroll
        for (int mt = 0; mt < 2; ++mt) {
            int row = m0 + warp_m * 32 + mt * 16 + (lane >> 2);
            #pragma unroll
            for (int nt = 0; nt < 4; ++nt) {
                int col = n0 + warp_n * 32 + nt * 8 + (lane & 3) * 2;
                *reinterpret_cast<float2*>(Db + (size_t)row * ldd + col) =
                    make_float2(acc[mt][nt][0], acc[mt][nt][1]);
                *reinterpret_cast<float2*>(Db + (size_t)(row + 8) * ldd + col) =
                    make_float2(acc[mt][nt][2], acc[mt][nt][3]);
            }
        }
    };

    // prologue: unit 0 in flight
    load_unit(tl, cl, 0);
    bool lmore = adv<G1>(tl, cl, nkl, NT);

    int u = 0;
    while (true) {
        __syncthreads();                       // WAR: stage (u+1)&1 free
        if (lmore) { load_unit(tl, cl, (u + 1) & 1); lmore = adv<G1>(tl, cl, nkl, NT); }
        else       { CP_COMMIT(); }
        CP_WAIT1();                            // unit u resident
        __syncthreads();                       // visibility

        if (cc == 0) {
            #pragma unroll
            for (int i = 0; i < 2; ++i)
                #pragma unroll
                for (int j = 0; j < 4; ++j)
                    #pragma unroll
                    for (int q = 0; q < 4; ++q) acc[i][j][q] = 0.0f;
        }
        compute_unit(u & 1);
        if (cc == nkc - 1) epilogue(tc);

        if (!adv<G1>(tc, cc, nkc, NT)) break;
        u++;
    }
}

// ---------------------------------------------------------------------------
// Softmax over compacted columns j < cnt; skips 128-col chunks >= npad.
// ---------------------------------------------------------------------------
__global__ void __launch_bounds__(256) softmax_split()
{
    const int row  = blockIdx.x * 8 + (threadIdx.x >> 5);
    const int lane = threadIdx.x & 31;
    const int b    = row >> 9;
    const int cnt  = g_cnt[b];
    const int npad = g_npad[b];

    const float* p = g_scores + (size_t)row * S_DIM;

    float4 fv[4];
    float mx = -3e38f;
    #pragma unroll
    for (int c = 0; c < 4; ++c) {
        if (c * 128 < npad) {
            const int s = c * 128 + lane * 4;
            float4 x = *reinterpret_cast<const float4*>(p + s);
            x.x = (s + 0 < cnt) ? x.x : NEG_INF_F;
            x.y = (s + 1 < cnt) ? x.y : NEG_INF_F;
            x.z = (s + 2 < cnt) ? x.z : NEG_INF_F;
            x.w = (s + 3 < cnt) ? x.w : NEG_INF_F;
            fv[c] = x;
            mx = fmaxf(mx, fmaxf(fmaxf(x.x, x.y), fmaxf(x.z, x.w)));
        } else {
            fv[c] = make_float4(NEG_INF_F, NEG_INF_F, NEG_INF_F, NEG_INF_F);
        }
    }
    #pragma unroll
    for (int o = 16; o > 0; o >>= 1) mx = fmaxf(mx, __shfl_xor_sync(0xffffffffu, mx, o));

    float sum = 0.0f;
    #pragma unroll
    for (int c = 0; c < 4; ++c) {
        if (c * 128 < npad) {
            fv[c].x = expf(fv[c].x - mx); fv[c].y = expf(fv[c].y - mx);
            fv[c].z = expf(fv[c].z - mx); fv[c].w = expf(fv[c].w - mx);
            sum += fv[c].x + fv[c].y + fv[c].z + fv[c].w;
        }
    }
    #pragma unroll
    for (int o = 16; o > 0; o >>= 1) sum += __shfl_xor_sync(0xffffffffu, sum, o);

    const float inv = 1.0f / sum;
    #pragma unroll
    for (int c = 0; c < 4; ++c) {
        if (c * 128 < npad) {
            const int s = c * 128 + lane * 4;
            float v0 = fv[c].x * inv, v1 = fv[c].y * inv, v2 = fv[c].z * inv, v3 = fv[c].w * inv;
            __nv_bfloat16 h0, l0, h1, l1, h2, l2, h3, l3;
            split2(v0, h0, l0); split2(v1, h1, l1); split2(v2, h2, l2); split2(v3, h3, l3);
            __nv_bfloat162* ph = reinterpret_cast<__nv_bfloat162*>(g_Ph + (size_t)row * S_DIM + s);
            __nv_bfloat162* pl = reinterpret_cast<__nv_bfloat162*>(g_Pl + (size_t)row * S_DIM + s);
            ph[0] = __nv_bfloat162{h0, h1}; ph[1] = __nv_bfloat162{h2, h3};
            pl[0] = __nv_bfloat162{l0, l1}; pl[1] = __nv_bfloat162{l2, l3};
        }
    }
}

// ---------------------------------------------------------------------------
// Launch
// ---------------------------------------------------------------------------
extern "C" void kernel_launch(void* const* d_in, const int* in_sizes, int n_in,
                              void* d_out, int out_size)
{
    const float* X    = (const float*)d_in[0];   // [B, S, H]
    const int*   mask = (const int*)  d_in[1];   // [B, S]
    const float* W    = (const float*)d_in[2];   // [L, H]
    float* out = (float*)d_out;                  // [B, L, H]

    cudaFuncSetAttribute(gemm_persist<true>,
                         cudaFuncAttributeMaxDynamicSharedMemorySize, GEMM_SMEM);
    cudaFuncSetAttribute(gemm_persist<false>,
                         cudaFuncAttributeMaxDynamicSharedMemorySize, GEMM_SMEM);

    void *pXh, *pXl, *pWh, *pWl, *pPh, *pPl, *pSc;
    cudaGetSymbolAddress(&pXh, g_Xh); cudaGetSymbolAddress(&pXl, g_Xl);
    cudaGetSymbolAddress(&pWh, g_Wh); cudaGetSymbolAddress(&pWl, g_Wl);
    cudaGetSymbolAddress(&pPh, g_Ph); cudaGetSymbolAddress(&pPl, g_Pl);
    cudaGetSymbolAddress(&pSc, g_scores);

    convert_W<<<(L_DIM * H_DIM) / 1024, 256>>>(W);
    compact_mask<<<B_DIM, 512>>>(mask);
    gather_convert_X<<<dim3(S_DIM, B_DIM), 256>>>(X);

    // GEMM1 (NT, persistent, compacted N): scores[b,l,j] = W[l,:] . Xc[b,j,:]
    gemm_persist<true><<<NCTA, 256, GEMM_SMEM>>>(
        (const __nv_bfloat16*)pWh, (const __nv_bfloat16*)pWl,
        (const __nv_bfloat16*)pXh, (const __nv_bfloat16*)pXl,
        (float*)pSc,
        H_DIM, H_DIM, S_DIM,
        0, (size_t)S_DIM * H_DIM, (size_t)L_DIM * S_DIM, NT1);

    softmax_split<<<(B_DIM * L_DIM) / 8, 256>>>();

    // GEMM2 (NN, persistent, compacted K): out[b,l,h] = Pc[b,l,:] . Xc[b,:,h]
    gemm_persist<false><<<NCTA, 256, GEMM_SMEM>>>(
        (const __nv_bfloat16*)pPh, (const __nv_bfloat16*)pPl,
        (const __nv_bfloat16*)pXh, (const __nv_bfloat16*)pXl,
        out,
        S_DIM, H_DIM, H_DIM,
        (size_t)L_DIM * S_DIM, (size_t)S_DIM * H_DIM, (size_t)L_DIM * H_DIM, NT2);
}

// round 11
// speedup vs baseline: 1.3915x; 1.3915x over previous
#include <cuda_runtime.h>
#include <cuda_bf16.h>
#include <stdint.h>

#define B_DIM 64
#define S_DIM 512
#define H_DIM 1024
#define L_DIM 512
#define NEG_INF_F (-1e9f)
#define NCTA 296

// ---------------------------------------------------------------------------
// Scratch (module-load allocations, allowed)
// ---------------------------------------------------------------------------
__device__ float         g_scores[(size_t)B_DIM * L_DIM * S_DIM];
__device__ __nv_bfloat16 g_Xh[(size_t)B_DIM * S_DIM * H_DIM];      // compacted
__device__ __nv_bfloat16 g_Xl[(size_t)B_DIM * S_DIM * H_DIM];
__device__ __nv_bfloat16 g_Wh[(size_t)L_DIM * H_DIM];
__device__ __nv_bfloat16 g_Wl[(size_t)L_DIM * H_DIM];
__device__ __nv_bfloat16 g_Ph[(size_t)B_DIM * L_DIM * S_DIM];      // compacted K
__device__ __nv_bfloat16 g_Pl[(size_t)B_DIM * L_DIM * S_DIM];
__device__ int g_idx[B_DIM * S_DIM];
__device__ int g_cnt[B_DIM];
__device__ int g_npad[B_DIM];          // cnt rounded up to 64
__device__ int g_off[B_DIM + 1];       // prefix over live G1 tiles (4*npad/64 per b)

// ---------------------------------------------------------------------------
// Helpers
// ---------------------------------------------------------------------------
__device__ __forceinline__ uint32_t smem_u32(const void* p) {
    uint32_t a;
    asm("{ .reg .u64 t; cvta.to.shared.u64 t, %1; cvt.u32.u64 %0, t; }" : "=r"(a) : "l"(p));
    return a;
}

#define CP_ASYNC16(dst, src) \
    asm volatile("cp.async.cg.shared.global [%0], [%1], 16;" :: "r"(dst), "l"(src))
#define CP_COMMIT()  asm volatile("cp.async.commit_group;" ::: "memory")
#define CP_WAIT1()   asm volatile("cp.async.wait_group 1;" ::: "memory")

#define LDSM_X4(r0, r1, r2, r3, a) \
    asm volatile("ldmatrix.sync.aligned.m8n8.x4.shared.b16 {%0,%1,%2,%3}, [%4];" \
        : "=r"(r0), "=r"(r1), "=r"(r2), "=r"(r3) : "r"(a))
#define LDSM_X4T(r0, r1, r2, r3, a) \
    asm volatile("ldmatrix.sync.aligned.m8n8.x4.trans.shared.b16 {%0,%1,%2,%3}, [%4];" \
        : "=r"(r0), "=r"(r1), "=r"(r2), "=r"(r3) : "r"(a))

#define MMA_BF16(d, a0, a1, a2, a3, b0, b1) \
    asm volatile("mma.sync.aligned.m16n8k16.row.col.f32.bf16.bf16.f32 " \
        "{%0,%1,%2,%3},{%4,%5,%6,%7},{%8,%9},{%0,%1,%2,%3};" \
        : "+f"((d)[0]), "+f"((d)[1]), "+f"((d)[2]), "+f"((d)[3]) \
        : "r"(a0), "r"(a1), "r"(a2), "r"(a3), "r"(b0), "r"(b1))

#define SWZ128(o) ((o) ^ (((o) >> 3) & 0x70))

__device__ __forceinline__ void split2(float v, __nv_bfloat16& h, __nv_bfloat16& l) {
    h = __float2bfloat16(v);
    l = __float2bfloat16(v - __bfloat162float(h));
}

// ---------------------------------------------------------------------------
// Mask compaction: one block of 512 threads per batch.
// ---------------------------------------------------------------------------
__global__ void __launch_bounds__(512) compact_mask(const int* __restrict__ mask) {
    const int b = blockIdx.x, tid = threadIdx.x;
    const int lane = tid & 31, w = tid >> 5;
    const int m = (mask[(size_t)b * S_DIM + tid] != 0);
    const unsigned bal = __ballot_sync(0xffffffffu, m);

    __shared__ int ws[16], woff[16];
    if (lane == 0) ws[w] = __popc(bal);
    __syncthreads();
    if (tid == 0) {
        int s = 0;
        #pragma unroll
        for (int i = 0; i < 16; ++i) { woff[i] = s; s += ws[i]; }
        g_cnt[b]  = s;
        int np = ((s + 63) >> 6) << 6;
        g_npad[b] = (np < 64) ? 64 : np;
    }
    __syncthreads();
    if (m) {
        int pos = woff[w] + __popc(bal & ((1u << lane) - 1u));
        g_idx[b * S_DIM + pos] = tid;
    }
}

// ---------------------------------------------------------------------------
// Prefix-scan of live G1 tile counts (4 * npad/64 per batch). One block, 64 thr.
// ---------------------------------------------------------------------------
__global__ void __launch_bounds__(64) scan_batches() {
    __shared__ int v[64];
    const int t = threadIdx.x;
    v[t] = (g_npad[t] >> 6) * 4;
    __syncthreads();
    for (int d = 1; d < 64; d <<= 1) {
        int x = (t >= d) ? v[t - d] : 0;
        __syncthreads();
        v[t] += x;
        __syncthreads();
    }
    g_off[t + 1] = v[t];
    if (t == 0) g_off[0] = 0;
}

// ---------------------------------------------------------------------------
// Gather + split-convert X. Rows j >= npad are never read by either GEMM.
// ---------------------------------------------------------------------------
__global__ void __launch_bounds__(256) gather_convert_X(const float* __restrict__ X) {
    const int j = blockIdx.x, b = blockIdx.y;
    if (j >= g_npad[b]) return;
    const int cnt = g_cnt[b];
    const size_t o = ((size_t)b * S_DIM + j) * H_DIM + threadIdx.x * 4;
    if (j < cnt) {
        const int s = g_idx[b * S_DIM + j];
        float4 v = *reinterpret_cast<const float4*>(X + ((size_t)b * S_DIM + s) * H_DIM + threadIdx.x * 4);
        __nv_bfloat16 h0, l0, h1, l1, h2, l2, h3, l3;
        split2(v.x, h0, l0); split2(v.y, h1, l1); split2(v.z, h2, l2); split2(v.w, h3, l3);
        *reinterpret_cast<__nv_bfloat162*>(g_Xh + o)     = __nv_bfloat162{h0, h1};
        *reinterpret_cast<__nv_bfloat162*>(g_Xh + o + 2) = __nv_bfloat162{h2, h3};
        *reinterpret_cast<__nv_bfloat162*>(g_Xl + o)     = __nv_bfloat162{l0, l1};
        *reinterpret_cast<__nv_bfloat162*>(g_Xl + o + 2) = __nv_bfloat162{l2, l3};
    } else {
        *reinterpret_cast<uint2*>(g_Xh + o) = make_uint2(0, 0);
        *reinterpret_cast<uint2*>(g_Xl + o) = make_uint2(0, 0);
    }
}

__global__ void convert_W(const float* __restrict__ W) {
    size_t i = ((size_t)blockIdx.x * 256 + threadIdx.x) * 4;
    float4 v = *reinterpret_cast<const float4*>(W + i);
    __nv_bfloat16 h0, l0, h1, l1, h2, l2, h3, l3;
    split2(v.x, h0, l0); split2(v.y, h1, l1); split2(v.z, h2, l2); split2(v.w, h3, l3);
    *reinterpret_cast<__nv_bfloat162*>(g_Wh + i)     = __nv_bfloat162{h0, h1};
    *reinterpret_cast<__nv_bfloat162*>(g_Wh + i + 2) = __nv_bfloat162{h2, h3};
    *reinterpret_cast<__nv_bfloat162*>(g_Wl + i)     = __nv_bfloat162{l0, l1};
    *reinterpret_cast<__nv_bfloat162*>(g_Wl + i + 2) = __nv_bfloat162{l2, l3};
}

#define STAGE_BYTES 49152
#define GEMM_SMEM   (2 * STAGE_BYTES)

// ---------------------------------------------------------------------------
// GEMM1: persistent, balanced over the dense live-tile list.
// CTA tile 128(M=L) x 64(N=j), warp 32x32, 8 warps, 2 CTAs/SM, nk = 16.
// Live tile g -> (b via g_off binary search, r = g-off; x = r % nx, y = r / nx).
// Load stream runs one chunk ahead of compute across tile boundaries.
// ---------------------------------------------------------------------------
__device__ __forceinline__ void map_tile(int g, int& b, int& m0, int& n0) {
    int lo = 0, hi = 64;
    while (hi - lo > 1) { int mid = (lo + hi) >> 1; if (g_off[mid] <= g) lo = mid; else hi = mid; }
    b = lo;
    int r = g - g_off[lo];
    int nx = g_npad[lo] >> 6;
    n0 = (r % nx) << 6;
    m0 = (r / nx) << 7;
}

__global__ void __launch_bounds__(256, 2) gemm1_persist()
{
    extern __shared__ char smem[];
    const uint32_t sb = smem_u32(smem);
    const int tid = threadIdx.x;
    const int wid = tid >> 5, lane = tid & 31;
    const int warp_m = wid & 3, warp_n = wid >> 2;

    const int total = g_off[64];
    const int lo = (int)((long long)blockIdx.x * total / NCTA);
    const int hi = (int)((long long)(blockIdx.x + 1) * total / NCTA);
    if (lo >= hi) return;

    int il = lo, cl = 0, bl, m0l, n0l;  map_tile(il, bl, m0l, n0l);
    int ic = lo, cc = 0, bc, m0c, n0c;  map_tile(ic, bc, m0c, n0c);
    bool lmore = true;

    float acc[2][4][4];

    auto load_unit = [&](int b, int m0, int n0, int c, int st) {
        const __nv_bfloat16* tAh = g_Wh + (size_t)m0 * H_DIM;
        const __nv_bfloat16* tAl = g_Wl + (size_t)m0 * H_DIM;
        const __nv_bfloat16* tBh = g_Xh + (size_t)b * S_DIM * H_DIM + (size_t)n0 * H_DIM;
        const __nv_bfloat16* tBl = g_Xl + (size_t)b * S_DIM * H_DIM + (size_t)n0 * H_DIM;
        const uint32_t base = sb + st * STAGE_BYTES;
        #pragma unroll
        for (int i = 0; i < 4; ++i) {
            int idx = i * 256 + tid;
            int row = idx >> 3, sl = idx & 7;
            uint32_t doff = SWZ128(row * 128 + sl * 16);
            CP_ASYNC16(base + doff,         tAh + (size_t)row * H_DIM + c * 64 + sl * 8);
            CP_ASYNC16(base + 16384 + doff, tAl + (size_t)row * H_DIM + c * 64 + sl * 8);
        }
        #pragma unroll
        for (int i = 0; i < 2; ++i) {
            int idx = i * 256 + tid;
            int row = idx >> 3, sl = idx & 7;
            uint32_t doff = SWZ128(row * 128 + sl * 16);
            CP_ASYNC16(base + 32768 + doff, tBh + (size_t)row * H_DIM + c * 64 + sl * 8);
            CP_ASYNC16(base + 40960 + doff, tBl + (size_t)row * H_DIM + c * 64 + sl * 8);
        }
        CP_COMMIT();
    };

    auto ladv = [&]() {
        if (++cl == 16) { cl = 0; if (++il >= hi) lmore = false; else map_tile(il, bl, m0l, n0l); }
    };

    auto compute_unit = [&](int st) {
        const uint32_t base = sb + st * STAGE_BYTES;
        const uint32_t sAh = base, sAl = base + 16384;
        const uint32_t sBh = base + 32768, sBl = base + 40960;
        #pragma unroll
        for (int ks = 0; ks < 4; ++ks) {
            uint32_t ah[2][4], al[2][4];
            #pragma unroll
            for (int mt = 0; mt < 2; ++mt) {
                int row = warp_m * 32 + mt * 16 + (lane & 15);
                uint32_t off = SWZ128(row * 128 + ks * 32 + ((lane >> 4) << 4));
                LDSM_X4(ah[mt][0], ah[mt][1], ah[mt][2], ah[mt][3], sAh + off);
                LDSM_X4(al[mt][0], al[mt][1], al[mt][2], al[mt][3], sAl + off);
            }
            uint32_t bh[4][2], bl2[4][2];
            #pragma unroll
            for (int nt2 = 0; nt2 < 2; ++nt2) {
                int row = warp_n * 32 + nt2 * 16 + ((lane >> 4) << 3) + (lane & 7);
                uint32_t off = SWZ128(row * 128 + ks * 32 + (((lane >> 3) & 1) << 4));
                LDSM_X4(bh[2 * nt2][0], bh[2 * nt2][1], bh[2 * nt2 + 1][0], bh[2 * nt2 + 1][1], sBh + off);
                LDSM_X4(bl2[2 * nt2][0], bl2[2 * nt2][1], bl2[2 * nt2 + 1][0], bl2[2 * nt2 + 1][1], sBl + off);
            }
            #pragma unroll
            for (int mt = 0; mt < 2; ++mt)
                #pragma unroll
                for (int nt = 0; nt < 4; ++nt) {
                    MMA_BF16(acc[mt][nt], ah[mt][0], ah[mt][1], ah[mt][2], ah[mt][3], bh[nt][0], bh[nt][1]);
                    MMA_BF16(acc[mt][nt], ah[mt][0], ah[mt][1], ah[mt][2], ah[mt][3], bl2[nt][0], bl2[nt][1]);
                    MMA_BF16(acc[mt][nt], al[mt][0], al[mt][1], al[mt][2], al[mt][3], bh[nt][0], bh[nt][1]);
                }
        }
    };

    auto epilogue = [&](int b, int m0, int n0) {
        float* Db = g_scores + (size_t)b * L_DIM * S_DIM;
        #pragma unroll
        for (int mt = 0; mt < 2; ++mt) {
            int row = m0 + warp_m * 32 + mt * 16 + (lane >> 2);
            #pragma unroll
            for (int nt = 0; nt < 4; ++nt) {
                int col = n0 + warp_n * 32 + nt * 8 + (lane & 3) * 2;
                *reinterpret_cast<float2*>(Db + (size_t)row * S_DIM + col) =
                    make_float2(acc[mt][nt][0], acc[mt][nt][1]);
                *reinterpret_cast<float2*>(Db + (size_t)(row + 8) * S_DIM + col) =
                    make_float2(acc[mt][nt][2], acc[mt][nt][3]);
            }
        }
    };

    load_unit(bl, m0l, n0l, cl, 0);
    ladv();

    int u = 0;
    while (true) {
        __syncthreads();                   // WAR: stage (u+1)&1 free (chunk u-1 done)
        if (lmore) { load_unit(bl, m0l, n0l, cl, (u + 1) & 1); ladv(); }
        else       { CP_COMMIT(); }
        CP_WAIT1();                        // chunk u resident
        __syncthreads();

        if (cc == 0) {
            #pragma unroll
            for (int i = 0; i < 2; ++i)
                #pragma unroll
                for (int j = 0; j < 4; ++j)
                    #pragma unroll
                    for (int q = 0; q < 4; ++q) acc[i][j][q] = 0.0f;
        }
        compute_unit(u & 1);
        if (cc == 15) epilogue(bc, m0c, n0c);

        if (++cc == 16) { cc = 0; if (++ic >= hi) break; map_tile(ic, bc, m0c, n0c); }
        u++;
    }
}

// ---------------------------------------------------------------------------
// GEMM2 (R9-proven): CTA 128(M) x 64(N), K-chunk 64, warp 32x32, 2 CTAs/SM,
// B row-major (ldmatrix trans), nk = npad[b]/64.
// ---------------------------------------------------------------------------
__global__ void __launch_bounds__(256, 2) gemm2_hmma(
    const __nv_bfloat16* __restrict__ Ah, const __nv_bfloat16* __restrict__ Al,
    const __nv_bfloat16* __restrict__ Bh, const __nv_bfloat16* __restrict__ Bl,
    float* __restrict__ D)
{
    extern __shared__ char smem[];
    const uint32_t sb = smem_u32(smem);
    const int tid = threadIdx.x;
    const int wid = tid >> 5, lane = tid & 31;
    const int warp_m = wid & 3, warp_n = wid >> 2;
    const int b  = blockIdx.z;
    const int m0 = blockIdx.y * 128;
    const int n0 = blockIdx.x * 64;
    const int nk = g_npad[b] >> 6;

    const __nv_bfloat16* tAh = Ah + (size_t)b * L_DIM * S_DIM + (size_t)m0 * S_DIM;
    const __nv_bfloat16* tAl = Al + (size_t)b * L_DIM * S_DIM + (size_t)m0 * S_DIM;
    const __nv_bfloat16* pBh = Bh + (size_t)b * S_DIM * H_DIM;
    const __nv_bfloat16* pBl = Bl + (size_t)b * S_DIM * H_DIM;

    float acc[2][4][4];
    #pragma unroll
    for (int i = 0; i < 2; ++i)
        #pragma unroll
        for (int j = 0; j < 4; ++j)
            #pragma unroll
            for (int q = 0; q < 4; ++q) acc[i][j][q] = 0.0f;

    auto load_stage = [&](int c, int st) {
        const uint32_t base = sb + st * STAGE_BYTES;
        #pragma unroll
        for (int i = 0; i < 4; ++i) {
            int idx = i * 256 + tid;
            int row = idx >> 3, sl = idx & 7;
            uint32_t doff = SWZ128(row * 128 + sl * 16);
            CP_ASYNC16(base + doff,         tAh + (size_t)row * S_DIM + c * 64 + sl * 8);
            CP_ASYNC16(base + 16384 + doff, tAl + (size_t)row * S_DIM + c * 64 + sl * 8);
        }
        #pragma unroll
        for (int i = 0; i < 2; ++i) {
            int idx = i * 256 + tid;
            int row = idx >> 3, sl = idx & 7;
            uint32_t doff = SWZ128(row * 128 + sl * 16);
            CP_ASYNC16(base + 32768 + doff, pBh + (size_t)(c * 64 + row) * H_DIM + n0 + sl * 8);
            CP_ASYNC16(base + 40960 + doff, pBl + (size_t)(c * 64 + row) * H_DIM + n0 + sl * 8);
        }
        CP_COMMIT();
    };

    load_stage(0, 0);

    for (int c = 0; c < nk; ++c) {
        if (c + 1 < nk) load_stage(c + 1, (c + 1) & 1);
        else            CP_COMMIT();
        CP_WAIT1();
        __syncthreads();

        const uint32_t base = sb + (c & 1) * STAGE_BYTES;
        const uint32_t sAh = base, sAl = base + 16384;
        const uint32_t sBh = base + 32768, sBl = base + 40960;

        #pragma unroll
        for (int ks = 0; ks < 4; ++ks) {
            uint32_t ah[2][4], al[2][4];
            #pragma unroll
            for (int mt = 0; mt < 2; ++mt) {
                int row = warp_m * 32 + mt * 16 + (lane & 15);
                uint32_t off = SWZ128(row * 128 + ks * 32 + ((lane >> 4) << 4));
                LDSM_X4(ah[mt][0], ah[mt][1], ah[mt][2], ah[mt][3], sAh + off);
                LDSM_X4(al[mt][0], al[mt][1], al[mt][2], al[mt][3], sAl + off);
            }
            uint32_t bh[4][2], bl2[4][2];
            #pragma unroll
            for (int nt2 = 0; nt2 < 2; ++nt2) {
                int krow = ks * 16 + (((lane >> 3) & 1) << 3) + (lane & 7);
                int col  = warp_n * 32 + nt2 * 16 + ((lane >> 4) << 3);
                uint32_t off = SWZ128(krow * 128 + col * 2);
                LDSM_X4T(bh[2 * nt2][0], bh[2 * nt2][1], bh[2 * nt2 + 1][0], bh[2 * nt2 + 1][1], sBh + off);
                LDSM_X4T(bl2[2 * nt2][0], bl2[2 * nt2][1], bl2[2 * nt2 + 1][0], bl2[2 * nt2 + 1][1], sBl + off);
            }
            #pragma unroll
            for (int mt = 0; mt < 2; ++mt)
                #pragma unroll
                for (int nt = 0; nt < 4; ++nt) {
                    MMA_BF16(acc[mt][nt], ah[mt][0], ah[mt][1], ah[mt][2], ah[mt][3], bh[nt][0], bh[nt][1]);
                    MMA_BF16(acc[mt][nt], ah[mt][0], ah[mt][1], ah[mt][2], ah[mt][3], bl2[nt][0], bl2[nt][1]);
                    MMA_BF16(acc[mt][nt], al[mt][0], al[mt][1], al[mt][2], al[mt][3], bh[nt][0], bh[nt][1]);
                }
        }
        __syncthreads();
    }

    float* Db = D + (size_t)b * L_DIM * H_DIM;
    #pragma unroll
    for (int mt = 0; mt < 2; ++mt) {
        int row = m0 + warp_m * 32 + mt * 16 + (lane >> 2);
        #pragma unroll
        for (int nt = 0; nt < 4; ++nt) {
            int col = n0 + warp_n * 32 + nt * 8 + (lane & 3) * 2;
            *reinterpret_cast<float2*>(Db + (size_t)row * H_DIM + col) =
                make_float2(acc[mt][nt][0], acc[mt][nt][1]);
            *reinterpret_cast<float2*>(Db + (size_t)(row + 8) * H_DIM + col) =
                make_float2(acc[mt][nt][2], acc[mt][nt][3]);
        }
    }
}

// ---------------------------------------------------------------------------
// Softmax over compacted columns j < cnt; skips 128-col chunks >= npad.
// ---------------------------------------------------------------------------
__global__ void __launch_bounds__(256) softmax_split()
{
    const int row  = blockIdx.x * 8 + (threadIdx.x >> 5);
    const int lane = threadIdx.x & 31;
    const int b    = row >> 9;
    const int cnt  = g_cnt[b];
    const int npad = g_npad[b];

    const float* p = g_scores + (size_t)row * S_DIM;

    float4 fv[4];
    float mx = -3e38f;
    #pragma unroll
    for (int c = 0; c < 4; ++c) {
        if (c * 128 < npad) {
            const int s = c * 128 + lane * 4;
            float4 x = *reinterpret_cast<const float4*>(p + s);
            x.x = (s + 0 < cnt) ? x.x : NEG_INF_F;
            x.y = (s + 1 < cnt) ? x.y : NEG_INF_F;
            x.z = (s + 2 < cnt) ? x.z : NEG_INF_F;
            x.w = (s + 3 < cnt) ? x.w : NEG_INF_F;
            fv[c] = x;
            mx = fmaxf(mx, fmaxf(fmaxf(x.x, x.y), fmaxf(x.z, x.w)));
        } else {
            fv[c] = make_float4(NEG_INF_F, NEG_INF_F, NEG_INF_F, NEG_INF_F);
        }
    }
    #pragma unroll
    for (int o = 16; o > 0; o >>= 1) mx = fmaxf(mx, __shfl_xor_sync(0xffffffffu, mx, o));

    float sum = 0.0f;
    #pragma unroll
    for (int c = 0; c < 4; ++c) {
        if (c * 128 < npad) {
            fv[c].x = expf(fv[c].x - mx); fv[c].y = expf(fv[c].y - mx);
            fv[c].z = expf(fv[c].z - mx); fv[c].w = expf(fv[c].w - mx);
            sum += fv[c].x + fv[c].y + fv[c].z + fv[c].w;
        }
    }
    #pragma unroll
    for (int o = 16; o > 0; o >>= 1) sum += __shfl_xor_sync(0xffffffffu, sum, o);

    const float inv = 1.0f / sum;
    #pragma unroll
    for (int c = 0; c < 4; ++c) {
        if (c * 128 < npad) {
            const int s = c * 128 + lane * 4;
            float v0 = fv[c].x * inv, v1 = fv[c].y * inv, v2 = fv[c].z * inv, v3 = fv[c].w * inv;
            __nv_bfloat16 h0, l0, h1, l1, h2, l2, h3, l3;
            split2(v0, h0, l0); split2(v1, h1, l1); split2(v2, h2, l2); split2(v3, h3, l3);
            __nv_bfloat162* ph = reinterpret_cast<__nv_bfloat162*>(g_Ph + (size_t)row * S_DIM + s);
            __nv_bfloat162* pl = reinterpret_cast<__nv_bfloat162*>(g_Pl + (size_t)row * S_DIM + s);
            ph[0] = __nv_bfloat162{h0, h1}; ph[1] = __nv_bfloat162{h2, h3};
            pl[0] = __nv_bfloat162{l0, l1}; pl[1] = __nv_bfloat162{l2, l3};
        }
    }
}

// ---------------------------------------------------------------------------
// Launch
// ---------------------------------------------------------------------------
extern "C" void kernel_launch(void* const* d_in, const int* in_sizes, int n_in,
                              void* d_out, int out_size)
{
    const float* X    = (const float*)d_in[0];   // [B, S, H]
    const int*   mask = (const int*)  d_in[1];   // [B, S]
    const float* W    = (const float*)d_in[2];   // [L, H]
    float* out = (float*)d_out;                  // [B, L, H]

    cudaFuncSetAttribute(gemm1_persist, cudaFuncAttributeMaxDynamicSharedMemorySize, GEMM_SMEM);
    cudaFuncSetAttribute(gemm2_hmma,    cudaFuncAttributeMaxDynamicSharedMemorySize, GEMM_SMEM);

    void *pXh, *pXl, *pPh, *pPl;
    cudaGetSymbolAddress(&pXh, g_Xh); cudaGetSymbolAddress(&pXl, g_Xl);
    cudaGetSymbolAddress(&pPh, g_Ph); cudaGetSymbolAddress(&pPl, g_Pl);

    convert_W<<<(L_DIM * H_DIM) / 1024, 256>>>(W);
    compact_mask<<<B_DIM, 512>>>(mask);
    scan_batches<<<1, 64>>>();
    gather_convert_X<<<dim3(S_DIM, B_DIM), 256>>>(X);

    // GEMM1 (persistent, balanced over dense live tiles)
    gemm1_persist<<<NCTA, 256, GEMM_SMEM>>>();

    softmax_split<<<(B_DIM * L_DIM) / 8, 256>>>();

    // GEMM2 (NN, compacted K): out[b,l,h] = Pc[b,l,:] . Xc[b,:,h]
    gemm2_hmma<<<dim3(H_DIM / 64, L_DIM / 128, B_DIM), 256, GEMM_SMEM>>>(
        (const __nv_bfloat16*)pPh, (const __nv_bfloat16*)pPl,
        (const __nv_bfloat16*)pXh, (const __nv_bfloat16*)pXl,
        out);
}

// round 12
// speedup vs baseline: 1.4529x; 1.0441x over previous
#include <cuda_runtime.h>
#include <cuda_bf16.h>
#include <stdint.h>

#define B_DIM 64
#define S_DIM 512
#define H_DIM 1024
#define L_DIM 512
#define NEG_INF_F (-1e9f)

// ---------------------------------------------------------------------------
// Scratch (module-load allocations, allowed)
// ---------------------------------------------------------------------------
__device__ float         g_scores[(size_t)B_DIM * L_DIM * S_DIM];
__device__ __nv_bfloat16 g_Xh[(size_t)B_DIM * S_DIM * H_DIM];      // compacted
__device__ __nv_bfloat16 g_Xl[(size_t)B_DIM * S_DIM * H_DIM];
__device__ __nv_bfloat16 g_Wh[(size_t)L_DIM * H_DIM];
__device__ __nv_bfloat16 g_Wl[(size_t)L_DIM * H_DIM];
__device__ __nv_bfloat16 g_Ph[(size_t)B_DIM * L_DIM * S_DIM];      // compacted K
__device__ __nv_bfloat16 g_Pl[(size_t)B_DIM * L_DIM * S_DIM];
__device__ int g_idx[B_DIM * S_DIM];
__device__ int g_cnt[B_DIM];
__device__ int g_npad[B_DIM];          // cnt rounded up to 64

// ---------------------------------------------------------------------------
// Helpers
// ---------------------------------------------------------------------------
__device__ __forceinline__ uint32_t smem_u32(const void* p) {
    uint32_t a;
    asm("{ .reg .u64 t; cvta.to.shared.u64 t, %1; cvt.u32.u64 %0, t; }" : "=r"(a) : "l"(p));
    return a;
}

#define CP_ASYNC16(dst, src) \
    asm volatile("cp.async.cg.shared.global [%0], [%1], 16;" :: "r"(dst), "l"(src))
#define CP_COMMIT()  asm volatile("cp.async.commit_group;" ::: "memory")
#define CP_WAIT1()   asm volatile("cp.async.wait_group 1;" ::: "memory")

#define LDSM_X4(r0, r1, r2, r3, a) \
    asm volatile("ldmatrix.sync.aligned.m8n8.x4.shared.b16 {%0,%1,%2,%3}, [%4];" \
        : "=r"(r0), "=r"(r1), "=r"(r2), "=r"(r3) : "r"(a))
#define LDSM_X4T(r0, r1, r2, r3, a) \
    asm volatile("ldmatrix.sync.aligned.m8n8.x4.trans.shared.b16 {%0,%1,%2,%3}, [%4];" \
        : "=r"(r0), "=r"(r1), "=r"(r2), "=r"(r3) : "r"(a))

#define MMA_BF16(d, a0, a1, a2, a3, b0, b1) \
    asm volatile("mma.sync.aligned.m16n8k16.row.col.f32.bf16.bf16.f32 " \
        "{%0,%1,%2,%3},{%4,%5,%6,%7},{%8,%9},{%0,%1,%2,%3};" \
        : "+f"((d)[0]), "+f"((d)[1]), "+f"((d)[2]), "+f"((d)[3]) \
        : "r"(a0), "r"(a1), "r"(a2), "r"(a3), "r"(b0), "r"(b1))

#define SWZ128(o) ((o) ^ (((o) >> 3) & 0x70))

__device__ __forceinline__ void split2(float v, __nv_bfloat16& h, __nv_bfloat16& l) {
    h = __float2bfloat16(v);
    l = __float2bfloat16(v - __bfloat162float(h));
}

// ---------------------------------------------------------------------------
// Mask compaction: one block of 512 threads per batch.
// ---------------------------------------------------------------------------
__global__ void __launch_bounds__(512) compact_mask(const int* __restrict__ mask) {
    const int b = blockIdx.x, tid = threadIdx.x;
    const int lane = tid & 31, w = tid >> 5;
    const int m = (mask[(size_t)b * S_DIM + tid] != 0);
    const unsigned bal = __ballot_sync(0xffffffffu, m);

    __shared__ int ws[16], woff[16];
    if (lane == 0) ws[w] = __popc(bal);
    __syncthreads();
    if (tid == 0) {
        int s = 0;
        #pragma unroll
        for (int i = 0; i < 16; ++i) { woff[i] = s; s += ws[i]; }
        g_cnt[b]  = s;
        int np = ((s + 63) >> 6) << 6;
        g_npad[b] = (np < 64) ? 64 : np;
    }
    __syncthreads();
    if (m) {
        int pos = woff[w] + __popc(bal & ((1u << lane) - 1u));
        g_idx[b * S_DIM + pos] = tid;
    }
}

// ---------------------------------------------------------------------------
// Gather + split-convert X, 4 rows per block. Rows j >= npad never read later.
// grid (S_DIM/4, B), 256 threads; each thread covers 4 floats of each row.
// ---------------------------------------------------------------------------
__global__ void __launch_bounds__(256) gather_convert_X(const float* __restrict__ X) {
    const int b = blockIdx.y;
    const int j0 = blockIdx.x * 4;
    const int npad = g_npad[b];
    if (j0 >= npad) return;
    const int cnt = g_cnt[b];
    const int col = threadIdx.x * 4;

    #pragma unroll
    for (int r = 0; r < 4; ++r) {
        const int j = j0 + r;
        if (j >= npad) break;
        const size_t o = ((size_t)b * S_DIM + j) * H_DIM + col;
        if (j < cnt) {
            const int s = g_idx[b * S_DIM + j];
            float4 v = *reinterpret_cast<const float4*>(
                X + ((size_t)b * S_DIM + s) * H_DIM + col);
            __nv_bfloat16 h0, l0, h1, l1, h2, l2, h3, l3;
            split2(v.x, h0, l0); split2(v.y, h1, l1); split2(v.z, h2, l2); split2(v.w, h3, l3);
            *reinterpret_cast<__nv_bfloat162*>(g_Xh + o)     = __nv_bfloat162{h0, h1};
            *reinterpret_cast<__nv_bfloat162*>(g_Xh + o + 2) = __nv_bfloat162{h2, h3};
            *reinterpret_cast<__nv_bfloat162*>(g_Xl + o)     = __nv_bfloat162{l0, l1};
            *reinterpret_cast<__nv_bfloat162*>(g_Xl + o + 2) = __nv_bfloat162{l2, l3};
        } else {
            *reinterpret_cast<uint2*>(g_Xh + o) = make_uint2(0, 0);
            *reinterpret_cast<uint2*>(g_Xl + o) = make_uint2(0, 0);
        }
    }
}

__global__ void convert_W(const float* __restrict__ W) {
    size_t i = ((size_t)blockIdx.x * 256 + threadIdx.x) * 4;
    float4 v = *reinterpret_cast<const float4*>(W + i);
    __nv_bfloat16 h0, l0, h1, l1, h2, l2, h3, l3;
    split2(v.x, h0, l0); split2(v.y, h1, l1); split2(v.z, h2, l2); split2(v.w, h3, l3);
    *reinterpret_cast<__nv_bfloat162*>(g_Wh + i)     = __nv_bfloat162{h0, h1};
    *reinterpret_cast<__nv_bfloat162*>(g_Wh + i + 2) = __nv_bfloat162{h2, h3};
    *reinterpret_cast<__nv_bfloat162*>(g_Wl + i)     = __nv_bfloat162{l0, l1};
    *reinterpret_cast<__nv_bfloat162*>(g_Wl + i + 2) = __nv_bfloat162{l2, l3};
}

// ---------------------------------------------------------------------------
// bf16x3 split GEMM via mma.sync (R9-proven). CTA 128(M) x 64(N), K-chunk 64,
// 8 warps (4M x 2N), warp tile 32x32. 2-stage cp.async pipeline, 2 CTAs/SM.
//   N_LIM: GEMM1 (B K-major), skip CTA if n0 >= npad
//   K_DYN: GEMM2 (B row-major), nk = npad/64
// smem/stage: Ah 16K | Al 16K | Bh 8K | Bl 8K = 48KB; 2 stages = 96KB.
// ---------------------------------------------------------------------------
#define STAGE_BYTES 49152
#define GEMM_SMEM   (2 * STAGE_BYTES)

template <bool B_KMAJOR, bool N_LIM, bool K_DYN>
__global__ void __launch_bounds__(256, 2) gemm_hmma_x3(
    const __nv_bfloat16* __restrict__ Ah, const __nv_bfloat16* __restrict__ Al,
    const __nv_bfloat16* __restrict__ Bh, const __nv_bfloat16* __restrict__ Bl,
    float* __restrict__ D,
    int lda, int ldb, int ldd, int nk,
    size_t strideA, size_t strideB, size_t strideD)
{
    extern __shared__ char smem[];
    const uint32_t sb = smem_u32(smem);
    const int tid = threadIdx.x;
    const int wid = tid >> 5, lane = tid & 31;
    const int warp_m = wid & 3, warp_n = wid >> 2;
    const int b  = blockIdx.z;
    const int m0 = blockIdx.y * 128;
    const int n0 = blockIdx.x * 64;

    if (N_LIM && n0 >= g_npad[b]) return;
    if (K_DYN) nk = g_npad[b] >> 6;

    const __nv_bfloat16* tAh = Ah + (size_t)b * strideA + (size_t)m0 * lda;
    const __nv_bfloat16* tAl = Al + (size_t)b * strideA + (size_t)m0 * lda;
    const __nv_bfloat16* pBh = Bh + (size_t)b * strideB;
    const __nv_bfloat16* pBl = Bl + (size_t)b * strideB;

    float acc[2][4][4];
    #pragma unroll
    for (int i = 0; i < 2; ++i)
        #pragma unroll
        for (int j = 0; j < 4; ++j)
            #pragma unroll
            for (int q = 0; q < 4; ++q) acc[i][j][q] = 0.0f;

    auto load_stage = [&](int c, int st) {
        const uint32_t base = sb + st * STAGE_BYTES;
        #pragma unroll
        for (int i = 0; i < 4; ++i) {
            int idx = i * 256 + tid;
            int row = idx >> 3, sl = idx & 7;
            uint32_t doff = SWZ128(row * 128 + sl * 16);
            CP_ASYNC16(base + doff,         tAh + (size_t)row * lda + c * 64 + sl * 8);
            CP_ASYNC16(base + 16384 + doff, tAl + (size_t)row * lda + c * 64 + sl * 8);
        }
        #pragma unroll
        for (int i = 0; i < 2; ++i) {
            int idx = i * 256 + tid;
            int row = idx >> 3, sl = idx & 7;
            uint32_t doff = SWZ128(row * 128 + sl * 16);
            if (B_KMAJOR) {
                CP_ASYNC16(base + 32768 + doff, pBh + (size_t)(n0 + row) * ldb + c * 64 + sl * 8);
                CP_ASYNC16(base + 40960 + doff, pBl + (size_t)(n0 + row) * ldb + c * 64 + sl * 8);
            } else {
                CP_ASYNC16(base + 32768 + doff, pBh + (size_t)(c * 64 + row) * ldb + n0 + sl * 8);
                CP_ASYNC16(base + 40960 + doff, pBl + (size_t)(c * 64 + row) * ldb + n0 + sl * 8);
            }
        }
        CP_COMMIT();
    };

    load_stage(0, 0);

    for (int c = 0; c < nk; ++c) {
        if (c + 1 < nk) load_stage(c + 1, (c + 1) & 1);
        else            CP_COMMIT();
        CP_WAIT1();
        __syncthreads();

        const uint32_t base = sb + (c & 1) * STAGE_BYTES;
        const uint32_t sAh = base, sAl = base + 16384;
        const uint32_t sBh = base + 32768, sBl = base + 40960;

        #pragma unroll
        for (int ks = 0; ks < 4; ++ks) {
            uint32_t ah[2][4], al[2][4];
            #pragma unroll
            for (int mt = 0; mt < 2; ++mt) {
                int row = warp_m * 32 + mt * 16 + (lane & 15);
                uint32_t off = SWZ128(row * 128 + ks * 32 + ((lane >> 4) << 4));
                LDSM_X4(ah[mt][0], ah[mt][1], ah[mt][2], ah[mt][3], sAh + off);
                LDSM_X4(al[mt][0], al[mt][1], al[mt][2], al[mt][3], sAl + off);
            }
            uint32_t bh[4][2], bl[4][2];
            #pragma unroll
            for (int nt2 = 0; nt2 < 2; ++nt2) {
                if (B_KMAJOR) {
                    int row = warp_n * 32 + nt2 * 16 + ((lane >> 4) << 3) + (lane & 7);
                    uint32_t off = SWZ128(row * 128 + ks * 32 + (((lane >> 3) & 1) << 4));
                    LDSM_X4(bh[2 * nt2][0], bh[2 * nt2][1], bh[2 * nt2 + 1][0], bh[2 * nt2 + 1][1], sBh + off);
                    LDSM_X4(bl[2 * nt2][0], bl[2 * nt2][1], bl[2 * nt2 + 1][0], bl[2 * nt2 + 1][1], sBl + off);
                } else {
                    int krow = ks * 16 + (((lane >> 3) & 1) << 3) + (lane & 7);
                    int col  = warp_n * 32 + nt2 * 16 + ((lane >> 4) << 3);
                    uint32_t off = SWZ128(krow * 128 + col * 2);
                    LDSM_X4T(bh[2 * nt2][0], bh[2 * nt2][1], bh[2 * nt2 + 1][0], bh[2 * nt2 + 1][1], sBh + off);
                    LDSM_X4T(bl[2 * nt2][0], bl[2 * nt2][1], bl[2 * nt2 + 1][0], bl[2 * nt2 + 1][1], sBl + off);
                }
            }
            #pragma unroll
            for (int mt = 0; mt < 2; ++mt)
                #pragma unroll
                for (int nt = 0; nt < 4; ++nt) {
                    MMA_BF16(acc[mt][nt], ah[mt][0], ah[mt][1], ah[mt][2], ah[mt][3], bh[nt][0], bh[nt][1]);
                    MMA_BF16(acc[mt][nt], ah[mt][0], ah[mt][1], ah[mt][2], ah[mt][3], bl[nt][0], bl[nt][1]);
                    MMA_BF16(acc[mt][nt], al[mt][0], al[mt][1], al[mt][2], al[mt][3], bh[nt][0], bh[nt][1]);
                }
        }
        __syncthreads();
    }

    float* Db = D + (size_t)b * strideD;
    #pragma unroll
    for (int mt = 0; mt < 2; ++mt) {
        int row = m0 + warp_m * 32 + mt * 16 + (lane >> 2);
        #pragma unroll
        for (int nt = 0; nt < 4; ++nt) {
            int col = n0 + warp_n * 32 + nt * 8 + (lane & 3) * 2;
            *reinterpret_cast<float2*>(Db + (size_t)row * ldd + col) =
                make_float2(acc[mt][nt][0], acc[mt][nt][1]);
            *reinterpret_cast<float2*>(Db + (size_t)(row + 8) * ldd + col) =
                make_float2(acc[mt][nt][2], acc[mt][nt][3]);
        }
    }
}

// ---------------------------------------------------------------------------
// Softmax over compacted columns j < cnt; skips 128-col chunks >= npad.
// ---------------------------------------------------------------------------
__global__ void __launch_bounds__(256) softmax_split()
{
    const int row  = blockIdx.x * 8 + (threadIdx.x >> 5);
    const int lane = threadIdx.x & 31;
    const int b    = row >> 9;
    const int cnt  = g_cnt[b];
    const int npad = g_npad[b];

    const float* p = g_scores + (size_t)row * S_DIM;

    float4 fv[4];
    float mx = -3e38f;
    #pragma unroll
    for (int c = 0; c < 4; ++c) {
        if (c * 128 < npad) {
            const int s = c * 128 + lane * 4;
            float4 x = *reinterpret_cast<const float4*>(p + s);
            x.x = (s + 0 < cnt) ? x.x : NEG_INF_F;
            x.y = (s + 1 < cnt) ? x.y : NEG_INF_F;
            x.z = (s + 2 < cnt) ? x.z : NEG_INF_F;
            x.w = (s + 3 < cnt) ? x.w : NEG_INF_F;
            fv[c] = x;
            mx = fmaxf(mx, fmaxf(fmaxf(x.x, x.y), fmaxf(x.z, x.w)));
        } else {
            fv[c] = make_float4(NEG_INF_F, NEG_INF_F, NEG_INF_F, NEG_INF_F);
        }
    }
    #pragma unroll
    for (int o = 16; o > 0; o >>= 1) mx = fmaxf(mx, __shfl_xor_sync(0xffffffffu, mx, o));

    float sum = 0.0f;
    #pragma unroll
    for (int c = 0; c < 4; ++c) {
        if (c * 128 < npad) {
            fv[c].x = expf(fv[c].x - mx); fv[c].y = expf(fv[c].y - mx);
            fv[c].z = expf(fv[c].z - mx); fv[c].w = expf(fv[c].w - mx);
            sum += fv[c].x + fv[c].y + fv[c].z + fv[c].w;
        }
    }
    #pragma unroll
    for (int o = 16; o > 0; o >>= 1) sum += __shfl_xor_sync(0xffffffffu, sum, o);

    const float inv = 1.0f / sum;
    #pragma unroll
    for (int c = 0; c < 4; ++c) {
        if (c * 128 < npad) {
            const int s = c * 128 + lane * 4;
            float v0 = fv[c].x * inv, v1 = fv[c].y * inv, v2 = fv[c].z * inv, v3 = fv[c].w * inv;
            __nv_bfloat16 h0, l0, h1, l1, h2, l2, h3, l3;
            split2(v0, h0, l0); split2(v1, h1, l1); split2(v2, h2, l2); split2(v3, h3, l3);
            __nv_bfloat162* ph = reinterpret_cast<__nv_bfloat162*>(g_Ph + (size_t)row * S_DIM + s);
            __nv_bfloat162* pl = reinterpret_cast<__nv_bfloat162*>(g_Pl + (size_t)row * S_DIM + s);
            ph[0] = __nv_bfloat162{h0, h1}; ph[1] = __nv_bfloat162{h2, h3};
            pl[0] = __nv_bfloat162{l0, l1}; pl[1] = __nv_bfloat162{l2, l3};
        }
    }
}

// ---------------------------------------------------------------------------
// Launch
// ---------------------------------------------------------------------------
extern "C" void kernel_launch(void* const* d_in, const int* in_sizes, int n_in,
                              void* d_out, int out_size)
{
    const float* X    = (const float*)d_in[0];   // [B, S, H]
    const int*   mask = (const int*)  d_in[1];   // [B, S]
    const float* W    = (const float*)d_in[2];   // [L, H]
    float* out = (float*)d_out;                  // [B, L, H]

    cudaFuncSetAttribute(gemm_hmma_x3<true, true, false>,
                         cudaFuncAttributeMaxDynamicSharedMemorySize, GEMM_SMEM);
    cudaFuncSetAttribute(gemm_hmma_x3<false, false, true>,
                         cudaFuncAttributeMaxDynamicSharedMemorySize, GEMM_SMEM);

    void *pXh, *pXl, *pWh, *pWl, *pPh, *pPl, *pSc;
    cudaGetSymbolAddress(&pXh, g_Xh); cudaGetSymbolAddress(&pXl, g_Xl);
    cudaGetSymbolAddress(&pWh, g_Wh); cudaGetSymbolAddress(&pWl, g_Wl);
    cudaGetSymbolAddress(&pPh, g_Ph); cudaGetSymbolAddress(&pPl, g_Pl);
    cudaGetSymbolAddress(&pSc, g_scores);

    convert_W<<<(L_DIM * H_DIM) / 1024, 256>>>(W);
    compact_mask<<<B_DIM, 512>>>(mask);
    gather_convert_X<<<dim3(S_DIM / 4, B_DIM), 256>>>(X);

    // GEMM1 (NT, compacted N, exact): scores[b,l,j] = W[l,:] . Xc[b,j,:]
    gemm_hmma_x3<true, true, false><<<dim3(S_DIM / 64, L_DIM / 128, B_DIM), 256, GEMM_SMEM>>>(
        (const __nv_bfloat16*)pWh, (const __nv_bfloat16*)pWl,
        (const __nv_bfloat16*)pXh, (const __nv_bfloat16*)pXl,
        (float*)pSc,
        H_DIM, H_DIM, S_DIM, H_DIM / 64,
        0, (size_t)S_DIM * H_DIM, (size_t)L_DIM * S_DIM);

    softmax_split<<<(B_DIM * L_DIM) / 8, 256>>>();

    // GEMM2 (NN, compacted K): out[b,l,h] = Pc[b,l,:] . Xc[b,:,h]
    gemm_hmma_x3<false, false, true><<<dim3(H_DIM / 64, L_DIM / 128, B_DIM), 256, GEMM_SMEM>>>(
        (const __nv_bfloat16*)pPh, (const __nv_bfloat16*)pPl,
        (const __nv_bfloat16*)pXh, (const __nv_bfloat16*)pXl,
        out,
        S_DIM, H_DIM, H_DIM, 0 /*K_DYN*/,
        (size_t)L_DIM * S_DIM, (size_t)S_DIM * H_DIM, (size_t)L_DIM * H_DIM);
}

// round 13
// speedup vs baseline: 1.4722x; 1.0132x over previous
#include <cuda_runtime.h>
#include <cuda_bf16.h>
#include <stdint.h>

#define B_DIM 64
#define S_DIM 512
#define H_DIM 1024
#define L_DIM 512
#define NEG_INF_F (-1e9f)

// ---------------------------------------------------------------------------
// Scratch (module-load allocations, allowed)
// ---------------------------------------------------------------------------
__device__ float         g_scores[(size_t)B_DIM * L_DIM * S_DIM];
__device__ __nv_bfloat16 g_Xh[(size_t)B_DIM * S_DIM * H_DIM];      // compacted
__device__ __nv_bfloat16 g_Xl[(size_t)B_DIM * S_DIM * H_DIM];
__device__ __nv_bfloat16 g_Wh[(size_t)L_DIM * H_DIM];
__device__ __nv_bfloat16 g_Wl[(size_t)L_DIM * H_DIM];
__device__ __nv_bfloat16 g_Ph[(size_t)B_DIM * L_DIM * S_DIM];      // compacted K
__device__ __nv_bfloat16 g_Pl[(size_t)B_DIM * L_DIM * S_DIM];
__device__ int g_idx[B_DIM * S_DIM];
__device__ int g_cnt[B_DIM];
__device__ int g_npad[B_DIM];          // cnt rounded up to 64

// ---------------------------------------------------------------------------
// Helpers
// ---------------------------------------------------------------------------
__device__ __forceinline__ uint32_t smem_u32(const void* p) {
    uint32_t a;
    asm("{ .reg .u64 t; cvta.to.shared.u64 t, %1; cvt.u32.u64 %0, t; }" : "=r"(a) : "l"(p));
    return a;
}

#define CP_ASYNC16(dst, src) \
    asm volatile("cp.async.cg.shared.global [%0], [%1], 16;" :: "r"(dst), "l"(src))
#define CP_COMMIT()  asm volatile("cp.async.commit_group;" ::: "memory")
#define CP_WAIT0()   asm volatile("cp.async.wait_group 0;" ::: "memory")

#define LDSM_X4(r0, r1, r2, r3, a) \
    asm volatile("ldmatrix.sync.aligned.m8n8.x4.shared.b16 {%0,%1,%2,%3}, [%4];" \
        : "=r"(r0), "=r"(r1), "=r"(r2), "=r"(r3) : "r"(a))
#define LDSM_X4T(r0, r1, r2, r3, a) \
    asm volatile("ldmatrix.sync.aligned.m8n8.x4.trans.shared.b16 {%0,%1,%2,%3}, [%4];" \
        : "=r"(r0), "=r"(r1), "=r"(r2), "=r"(r3) : "r"(a))

#define MMA_BF16(d, a0, a1, a2, a3, b0, b1) \
    asm volatile("mma.sync.aligned.m16n8k16.row.col.f32.bf16.bf16.f32 " \
        "{%0,%1,%2,%3},{%4,%5,%6,%7},{%8,%9},{%0,%1,%2,%3};" \
        : "+f"((d)[0]), "+f"((d)[1]), "+f"((d)[2]), "+f"((d)[3]) \
        : "r"(a0), "r"(a1), "r"(a2), "r"(a3), "r"(b0), "r"(b1))

#define SWZ128(o) ((o) ^ (((o) >> 3) & 0x70))

__device__ __forceinline__ void split2(float v, __nv_bfloat16& h, __nv_bfloat16& l) {
    h = __float2bfloat16(v);
    l = __float2bfloat16(v - __bfloat162float(h));
}

// ---------------------------------------------------------------------------
// Mask compaction: one block of 512 threads per batch.
// ---------------------------------------------------------------------------
__global__ void __launch_bounds__(512) compact_mask(const int* __restrict__ mask) {
    const int b = blockIdx.x, tid = threadIdx.x;
    const int lane = tid & 31, w = tid >> 5;
    const int m = (mask[(size_t)b * S_DIM + tid] != 0);
    const unsigned bal = __ballot_sync(0xffffffffu, m);

    __shared__ int ws[16], woff[16];
    if (lane == 0) ws[w] = __popc(bal);
    __syncthreads();
    if (tid == 0) {
        int s = 0;
        #pragma unroll
        for (int i = 0; i < 16; ++i) { woff[i] = s; s += ws[i]; }
        g_cnt[b]  = s;
        int np = ((s + 63) >> 6) << 6;
        g_npad[b] = (np < 64) ? 64 : np;
    }
    __syncthreads();
    if (m) {
        int pos = woff[w] + __popc(bal & ((1u << lane) - 1u));
        g_idx[b * S_DIM + pos] = tid;
    }
}

// ---------------------------------------------------------------------------
// Gather + split-convert X (4 rows/block), and convert W on the extra y-slice.
// grid (S_DIM/4, B_DIM + 1): y < B_DIM -> gather X rows; y == B_DIM -> W rows.
// ---------------------------------------------------------------------------
__global__ void __launch_bounds__(256) gather_convert(const float* __restrict__ X,
                                                      const float* __restrict__ W) {
    const int col = threadIdx.x * 4;
    if (blockIdx.y == B_DIM) {
        // convert W rows 4*bx .. 4*bx+3  (L=512 rows of H=1024)
        const int r0 = blockIdx.x * 4;
        #pragma unroll
        for (int r = 0; r < 4; ++r) {
            const size_t o = (size_t)(r0 + r) * H_DIM + col;
            float4 v = *reinterpret_cast<const float4*>(W + o);
            __nv_bfloat16 h0, l0, h1, l1, h2, l2, h3, l3;
            split2(v.x, h0, l0); split2(v.y, h1, l1); split2(v.z, h2, l2); split2(v.w, h3, l3);
            *reinterpret_cast<__nv_bfloat162*>(g_Wh + o)     = __nv_bfloat162{h0, h1};
            *reinterpret_cast<__nv_bfloat162*>(g_Wh + o + 2) = __nv_bfloat162{h2, h3};
            *reinterpret_cast<__nv_bfloat162*>(g_Wl + o)     = __nv_bfloat162{l0, l1};
            *reinterpret_cast<__nv_bfloat162*>(g_Wl + o + 2) = __nv_bfloat162{l2, l3};
        }
        return;
    }
    const int b = blockIdx.y;
    const int j0 = blockIdx.x * 4;
    const int npad = g_npad[b];
    if (j0 >= npad) return;
    const int cnt = g_cnt[b];

    #pragma unroll
    for (int r = 0; r < 4; ++r) {
        const int j = j0 + r;
        if (j >= npad) break;
        const size_t o = ((size_t)b * S_DIM + j) * H_DIM + col;
        if (j < cnt) {
            const int s = g_idx[b * S_DIM + j];
            float4 v = *reinterpret_cast<const float4*>(
                X + ((size_t)b * S_DIM + s) * H_DIM + col);
            __nv_bfloat16 h0, l0, h1, l1, h2, l2, h3, l3;
            split2(v.x, h0, l0); split2(v.y, h1, l1); split2(v.z, h2, l2); split2(v.w, h3, l3);
            *reinterpret_cast<__nv_bfloat162*>(g_Xh + o)     = __nv_bfloat162{h0, h1};
            *reinterpret_cast<__nv_bfloat162*>(g_Xh + o + 2) = __nv_bfloat162{h2, h3};
            *reinterpret_cast<__nv_bfloat162*>(g_Xl + o)     = __nv_bfloat162{l0, l1};
            *reinterpret_cast<__nv_bfloat162*>(g_Xl + o + 2) = __nv_bfloat162{l2, l3};
        } else {
            *reinterpret_cast<uint2*>(g_Xh + o) = make_uint2(0, 0);
            *reinterpret_cast<uint2*>(g_Xl + o) = make_uint2(0, 0);
        }
    }
}

// ---------------------------------------------------------------------------
// bf16x3 split GEMM via mma.sync. CTA 128(M) x 64(N), K-chunk 64, 8 warps
// (4M x 2N), warp tile 32x32. 2-stage cp.async pipeline with ONE barrier per
// chunk (WAIT0 -> sync -> issue next load -> compute), 2 CTAs/SM.
//   N_LIM: GEMM1 (B K-major), skip CTA if n0 >= npad
//   K_DYN: GEMM2 (B row-major), nk = npad/64
// ---------------------------------------------------------------------------
#define STAGE_BYTES 49152
#define GEMM_SMEM   (2 * STAGE_BYTES)

template <bool B_KMAJOR, bool N_LIM, bool K_DYN>
__global__ void __launch_bounds__(256, 2) gemm_hmma_x3(
    const __nv_bfloat16* __restrict__ Ah, const __nv_bfloat16* __restrict__ Al,
    const __nv_bfloat16* __restrict__ Bh, const __nv_bfloat16* __restrict__ Bl,
    float* __restrict__ D,
    int lda, int ldb, int ldd, int nk,
    size_t strideA, size_t strideB, size_t strideD)
{
    extern __shared__ char smem[];
    const uint32_t sb = smem_u32(smem);
    const int tid = threadIdx.x;
    const int wid = tid >> 5, lane = tid & 31;
    const int warp_m = wid & 3, warp_n = wid >> 2;
    const int b  = blockIdx.z;
    const int m0 = blockIdx.y * 128;
    const int n0 = blockIdx.x * 64;

    if (N_LIM && n0 >= g_npad[b]) return;
    if (K_DYN) nk = g_npad[b] >> 6;

    const __nv_bfloat16* tAh = Ah + (size_t)b * strideA + (size_t)m0 * lda;
    const __nv_bfloat16* tAl = Al + (size_t)b * strideA + (size_t)m0 * lda;
    const __nv_bfloat16* pBh = Bh + (size_t)b * strideB;
    const __nv_bfloat16* pBl = Bl + (size_t)b * strideB;

    float acc[2][4][4];
    #pragma unroll
    for (int i = 0; i < 2; ++i)
        #pragma unroll
        for (int j = 0; j < 4; ++j)
            #pragma unroll
            for (int q = 0; q < 4; ++q) acc[i][j][q] = 0.0f;

    auto load_stage = [&](int c, int st) {
        const uint32_t base = sb + st * STAGE_BYTES;
        #pragma unroll
        for (int i = 0; i < 4; ++i) {
            int idx = i * 256 + tid;
            int row = idx >> 3, sl = idx & 7;
            uint32_t doff = SWZ128(row * 128 + sl * 16);
            CP_ASYNC16(base + doff,         tAh + (size_t)row * lda + c * 64 + sl * 8);
            CP_ASYNC16(base + 16384 + doff, tAl + (size_t)row * lda + c * 64 + sl * 8);
        }
        #pragma unroll
        for (int i = 0; i < 2; ++i) {
            int idx = i * 256 + tid;
            int row = idx >> 3, sl = idx & 7;
            uint32_t doff = SWZ128(row * 128 + sl * 16);
            if (B_KMAJOR) {
                CP_ASYNC16(base + 32768 + doff, pBh + (size_t)(n0 + row) * ldb + c * 64 + sl * 8);
                CP_ASYNC16(base + 40960 + doff, pBl + (size_t)(n0 + row) * ldb + c * 64 + sl * 8);
            } else {
                CP_ASYNC16(base + 32768 + doff, pBh + (size_t)(c * 64 + row) * ldb + n0 + sl * 8);
                CP_ASYNC16(base + 40960 + doff, pBl + (size_t)(c * 64 + row) * ldb + n0 + sl * 8);
            }
        }
        CP_COMMIT();
    };

    // prologue: chunk 0 in flight
    load_stage(0, 0);

    for (int c = 0; c < nk; ++c) {
        CP_WAIT0();          // chunk c resident (issued last iter, overlapped compute(c-1))
        __syncthreads();     // visibility of c + WAR: all warps done with stage (c+1)&1
        if (c + 1 < nk) load_stage(c + 1, (c + 1) & 1);   // flies during compute(c)

        const uint32_t base = sb + (c & 1) * STAGE_BYTES;
        const uint32_t sAh = base, sAl = base + 16384;
        const uint32_t sBh = base + 32768, sBl = base + 40960;

        #pragma unroll
        for (int ks = 0; ks < 4; ++ks) {
            // --- hi fragments first ---
            uint32_t ah[2][4], bh[4][2];
            #pragma unroll
            for (int mt = 0; mt < 2; ++mt) {
                int row = warp_m * 32 + mt * 16 + (lane & 15);
                uint32_t off = SWZ128(row * 128 + ks * 32 + ((lane >> 4) << 4));
                LDSM_X4(ah[mt][0], ah[mt][1], ah[mt][2], ah[mt][3], sAh + off);
            }
            #pragma unroll
            for (int nt2 = 0; nt2 < 2; ++nt2) {
                if (B_KMAJOR) {
                    int row = warp_n * 32 + nt2 * 16 + ((lane >> 4) << 3) + (lane & 7);
                    uint32_t off = SWZ128(row * 128 + ks * 32 + (((lane >> 3) & 1) << 4));
                    LDSM_X4(bh[2 * nt2][0], bh[2 * nt2][1], bh[2 * nt2 + 1][0], bh[2 * nt2 + 1][1], sBh + off);
                } else {
                    int krow = ks * 16 + (((lane >> 3) & 1) << 3) + (lane & 7);
                    int col  = warp_n * 32 + nt2 * 16 + ((lane >> 4) << 3);
                    uint32_t off = SWZ128(krow * 128 + col * 2);
                    LDSM_X4T(bh[2 * nt2][0], bh[2 * nt2][1], bh[2 * nt2 + 1][0], bh[2 * nt2 + 1][1], sBh + off);
                }
            }
            // hh product (hides the lo-fragment loads below)
            #pragma unroll
            for (int mt = 0; mt < 2; ++mt)
                #pragma unroll
                for (int nt = 0; nt < 4; ++nt)
                    MMA_BF16(acc[mt][nt], ah[mt][0], ah[mt][1], ah[mt][2], ah[mt][3], bh[nt][0], bh[nt][1]);

            // --- lo fragments ---
            uint32_t al[2][4], bl[4][2];
            #pragma unroll
            for (int mt = 0; mt < 2; ++mt) {
                int row = warp_m * 32 + mt * 16 + (lane & 15);
                uint32_t off = SWZ128(row * 128 + ks * 32 + ((lane >> 4) << 4));
                LDSM_X4(al[mt][0], al[mt][1], al[mt][2], al[mt][3], sAl + off);
            }
            #pragma unroll
            for (int nt2 = 0; nt2 < 2; ++nt2) {
                if (B_KMAJOR) {
                    int row = warp_n * 32 + nt2 * 16 + ((lane >> 4) << 3) + (lane & 7);
                    uint32_t off = SWZ128(row * 128 + ks * 32 + (((lane >> 3) & 1) << 4));
                    LDSM_X4(bl[2 * nt2][0], bl[2 * nt2][1], bl[2 * nt2 + 1][0], bl[2 * nt2 + 1][1], sBl + off);
                } else {
                    int krow = ks * 16 + (((lane >> 3) & 1) << 3) + (lane & 7);
                    int col  = warp_n * 32 + nt2 * 16 + ((lane >> 4) << 3);
                    uint32_t off = SWZ128(krow * 128 + col * 2);
                    LDSM_X4T(bl[2 * nt2][0], bl[2 * nt2][1], bl[2 * nt2 + 1][0], bl[2 * nt2 + 1][1], sBl + off);
                }
            }
            // cross products
            #pragma unroll
            for (int mt = 0; mt < 2; ++mt)
                #pragma unroll
                for (int nt = 0; nt < 4; ++nt) {
                    MMA_BF16(acc[mt][nt], ah[mt][0], ah[mt][1], ah[mt][2], ah[mt][3], bl[nt][0], bl[nt][1]);
                    MMA_BF16(acc[mt][nt], al[mt][0], al[mt][1], al[mt][2], al[mt][3], bh[nt][0], bh[nt][1]);
                }
        }
    }

    float* Db = D + (size_t)b * strideD;
    #pragma unroll
    for (int mt = 0; mt < 2; ++mt) {
        int row = m0 + warp_m * 32 + mt * 16 + (lane >> 2);
        #pragma unroll
        for (int nt = 0; nt < 4; ++nt) {
            int col = n0 + warp_n * 32 + nt * 8 + (lane & 3) * 2;
            *reinterpret_cast<float2*>(Db + (size_t)row * ldd + col) =
                make_float2(acc[mt][nt][0], acc[mt][nt][1]);
            *reinterpret_cast<float2*>(Db + (size_t)(row + 8) * ldd + col) =
                make_float2(acc[mt][nt][2], acc[mt][nt][3]);
        }
    }
}

// ---------------------------------------------------------------------------
// Softmax over compacted columns j < cnt; skips 128-col chunks >= npad.
// ---------------------------------------------------------------------------
__global__ void __launch_bounds__(256) softmax_split()
{
    const int row  = blockIdx.x * 8 + (threadIdx.x >> 5);
    const int lane = threadIdx.x & 31;
    const int b    = row >> 9;
    const int cnt  = g_cnt[b];
    const int npad = g_npad[b];

    const float* p = g_scores + (size_t)row * S_DIM;

    float4 fv[4];
    float mx = -3e38f;
    #pragma unroll
    for (int c = 0; c < 4; ++c) {
        if (c * 128 < npad) {
            const int s = c * 128 + lane * 4;
            float4 x = *reinterpret_cast<const float4*>(p + s);
            x.x = (s + 0 < cnt) ? x.x : NEG_INF_F;
            x.y = (s + 1 < cnt) ? x.y : NEG_INF_F;
            x.z = (s + 2 < cnt) ? x.z : NEG_INF_F;
            x.w = (s + 3 < cnt) ? x.w : NEG_INF_F;
            fv[c] = x;
            mx = fmaxf(mx, fmaxf(fmaxf(x.x, x.y), fmaxf(x.z, x.w)));
        } else {
            fv[c] = make_float4(NEG_INF_F, NEG_INF_F, NEG_INF_F, NEG_INF_F);
        }
    }
    #pragma unroll
    for (int o = 16; o > 0; o >>= 1) mx = fmaxf(mx, __shfl_xor_sync(0xffffffffu, mx, o));

    float sum = 0.0f;
    #pragma unroll
    for (int c = 0; c < 4; ++c) {
        if (c * 128 < npad) {
            fv[c].x = expf(fv[c].x - mx); fv[c].y = expf(fv[c].y - mx);
            fv[c].z = expf(fv[c].z - mx); fv[c].w = expf(fv[c].w - mx);
            sum += fv[c].x + fv[c].y + fv[c].z + fv[c].w;
        }
    }
    #pragma unroll
    for (int o = 16; o > 0; o >>= 1) sum += __shfl_xor_sync(0xffffffffu, sum, o);

    const float inv = 1.0f / sum;
    #pragma unroll
    for (int c = 0; c < 4; ++c) {
        if (c * 128 < npad) {
            const int s = c * 128 + lane * 4;
            float v0 = fv[c].x * inv, v1 = fv[c].y * inv, v2 = fv[c].z * inv, v3 = fv[c].w * inv;
            __nv_bfloat16 h0, l0, h1, l1, h2, l2, h3, l3;
            split2(v0, h0, l0); split2(v1, h1, l1); split2(v2, h2, l2); split2(v3, h3, l3);
            __nv_bfloat162* ph = reinterpret_cast<__nv_bfloat162*>(g_Ph + (size_t)row * S_DIM + s);
            __nv_bfloat162* pl = reinterpret_cast<__nv_bfloat162*>(g_Pl + (size_t)row * S_DIM + s);
            ph[0] = __nv_bfloat162{h0, h1}; ph[1] = __nv_bfloat162{h2, h3};
            pl[0] = __nv_bfloat162{l0, l1}; pl[1] = __nv_bfloat162{l2, l3};
        }
    }
}

// ---------------------------------------------------------------------------
// Launch
// ---------------------------------------------------------------------------
extern "C" void kernel_launch(void* const* d_in, const int* in_sizes, int n_in,
                              void* d_out, int out_size)
{
    const float* X    = (const float*)d_in[0];   // [B, S, H]
    const int*   mask = (const int*)  d_in[1];   // [B, S]
    const float* W    = (const float*)d_in[2];   // [L, H]
    float* out = (float*)d_out;                  // [B, L, H]

    cudaFuncSetAttribute(gemm_hmma_x3<true, true, false>,
                         cudaFuncAttributeMaxDynamicSharedMemorySize, GEMM_SMEM);
    cudaFuncSetAttribute(gemm_hmma_x3<false, false, true>,
                         cudaFuncAttributeMaxDynamicSharedMemorySize, GEMM_SMEM);

    void *pXh, *pXl, *pWh, *pWl, *pPh, *pPl, *pSc;
    cudaGetSymbolAddress(&pXh, g_Xh); cudaGetSymbolAddress(&pXl, g_Xl);
    cudaGetSymbolAddress(&pWh, g_Wh); cudaGetSymbolAddress(&pWl, g_Wl);
    cudaGetSymbolAddress(&pPh, g_Ph); cudaGetSymbolAddress(&pPl, g_Pl);
    cudaGetSymbolAddress(&pSc, g_scores);

    compact_mask<<<B_DIM, 512>>>(mask);
    gather_convert<<<dim3(S_DIM / 4, B_DIM + 1), 256>>>(X, W);

    // GEMM1 (NT, compacted N, exact): scores[b,l,j] = W[l,:] . Xc[b,j,:]
    gemm_hmma_x3<true, true, false><<<dim3(S_DIM / 64, L_DIM / 128, B_DIM), 256, GEMM_SMEM>>>(
        (const __nv_bfloat16*)pWh, (const __nv_bfloat16*)pWl,
        (const __nv_bfloat16*)pXh, (const __nv_bfloat16*)pXl,
        (float*)pSc,
        H_DIM, H_DIM, S_DIM, H_DIM / 64,
        0, (size_t)S_DIM * H_DIM, (size_t)L_DIM * S_DIM);

    softmax_split<<<(B_DIM * L_DIM) / 8, 256>>>();

    // GEMM2 (NN, compacted K): out[b,l,h] = Pc[b,l,:] . Xc[b,:,h]
    gemm_hmma_x3<false, false, true><<<dim3(H_DIM / 64, L_DIM / 128, B_DIM), 256, GEMM_SMEM>>>(
        (const __nv_bfloat16*)pPh, (const __nv_bfloat16*)pPl,
        (const __nv_bfloat16*)pXh, (const __nv_bfloat16*)pXl,
        out,
        S_DIM, H_DIM, H_DIM, 0 /*K_DYN*/,
        (size_t)L_DIM * S_DIM, (size_t)S_DIM * H_DIM, (size_t)L_DIM * H_DIM);
}

// round 14
// speedup vs baseline: 1.4933x; 1.0144x over previous
#include <cuda_runtime.h>
#include <cuda_bf16.h>
#include <stdint.h>

#define B_DIM 64
#define S_DIM 512
#define H_DIM 1024
#define L_DIM 512
#define NEG_INF_F (-1e9f)

// ---------------------------------------------------------------------------
// Scratch (module-load allocations, allowed)
// ---------------------------------------------------------------------------
__device__ float         g_scores[(size_t)B_DIM * L_DIM * S_DIM];
__device__ __nv_bfloat16 g_Xh[(size_t)B_DIM * S_DIM * H_DIM];      // compacted
__device__ __nv_bfloat16 g_Xl[(size_t)B_DIM * S_DIM * H_DIM];
__device__ __nv_bfloat16 g_Wh[(size_t)L_DIM * H_DIM];
__device__ __nv_bfloat16 g_Wl[(size_t)L_DIM * H_DIM];
__device__ __nv_bfloat16 g_Ph[(size_t)B_DIM * L_DIM * S_DIM];      // compacted K
__device__ __nv_bfloat16 g_Pl[(size_t)B_DIM * L_DIM * S_DIM];
__device__ int g_idx[B_DIM * S_DIM];
__device__ int g_cnt[B_DIM];
__device__ int g_npad[B_DIM];          // cnt rounded up to 64

// ---------------------------------------------------------------------------
// Helpers
// ---------------------------------------------------------------------------
__device__ __forceinline__ uint32_t smem_u32(const void* p) {
    uint32_t a;
    asm("{ .reg .u64 t; cvta.to.shared.u64 t, %1; cvt.u32.u64 %0, t; }" : "=r"(a) : "l"(p));
    return a;
}

#define CP_ASYNC16(dst, src) \
    asm volatile("cp.async.cg.shared.global [%0], [%1], 16;" :: "r"(dst), "l"(src))
#define CP_COMMIT()  asm volatile("cp.async.commit_group;" ::: "memory")
#define CP_WAIT0()   asm volatile("cp.async.wait_group 0;" ::: "memory")

#define LDSM_X4(r0, r1, r2, r3, a) \
    asm volatile("ldmatrix.sync.aligned.m8n8.x4.shared.b16 {%0,%1,%2,%3}, [%4];" \
        : "=r"(r0), "=r"(r1), "=r"(r2), "=r"(r3) : "r"(a))
#define LDSM_X4T(r0, r1, r2, r3, a) \
    asm volatile("ldmatrix.sync.aligned.m8n8.x4.trans.shared.b16 {%0,%1,%2,%3}, [%4];" \
        : "=r"(r0), "=r"(r1), "=r"(r2), "=r"(r3) : "r"(a))

#define MMA_BF16(d, a0, a1, a2, a3, b0, b1) \
    asm volatile("mma.sync.aligned.m16n8k16.row.col.f32.bf16.bf16.f32 " \
        "{%0,%1,%2,%3},{%4,%5,%6,%7},{%8,%9},{%0,%1,%2,%3};" \
        : "+f"((d)[0]), "+f"((d)[1]), "+f"((d)[2]), "+f"((d)[3]) \
        : "r"(a0), "r"(a1), "r"(a2), "r"(a3), "r"(b0), "r"(b1))

#define SWZ128(o) ((o) ^ (((o) >> 3) & 0x70))

__device__ __forceinline__ void split2(float v, __nv_bfloat16& h, __nv_bfloat16& l) {
    h = __float2bfloat16(v);
    l = __float2bfloat16(v - __bfloat162float(h));
}

// ---------------------------------------------------------------------------
// Mask compaction: one block of 512 threads per batch.
// ---------------------------------------------------------------------------
__global__ void __launch_bounds__(512) compact_mask(const int* __restrict__ mask) {
    const int b = blockIdx.x, tid = threadIdx.x;
    const int lane = tid & 31, w = tid >> 5;
    const int m = (mask[(size_t)b * S_DIM + tid] != 0);
    const unsigned bal = __ballot_sync(0xffffffffu, m);

    __shared__ int ws[16], woff[16];
    if (lane == 0) ws[w] = __popc(bal);
    __syncthreads();
    if (tid == 0) {
        int s = 0;
        #pragma unroll
        for (int i = 0; i < 16; ++i) { woff[i] = s; s += ws[i]; }
        g_cnt[b]  = s;
        int np = ((s + 63) >> 6) << 6;
        g_npad[b] = (np < 64) ? 64 : np;
    }
    __syncthreads();
    if (m) {
        int pos = woff[w] + __popc(bal & ((1u << lane) - 1u));
        g_idx[b * S_DIM + pos] = tid;
    }
}

// ---------------------------------------------------------------------------
// Gather + split-convert X (4 rows/block), and convert W on the extra y-slice.
// ---------------------------------------------------------------------------
__global__ void __launch_bounds__(256) gather_convert(const float* __restrict__ X,
                                                      const float* __restrict__ W) {
    const int col = threadIdx.x * 4;
    if (blockIdx.y == B_DIM) {
        const int r0 = blockIdx.x * 4;
        #pragma unroll
        for (int r = 0; r < 4; ++r) {
            const size_t o = (size_t)(r0 + r) * H_DIM + col;
            float4 v = *reinterpret_cast<const float4*>(W + o);
            __nv_bfloat16 h0, l0, h1, l1, h2, l2, h3, l3;
            split2(v.x, h0, l0); split2(v.y, h1, l1); split2(v.z, h2, l2); split2(v.w, h3, l3);
            *reinterpret_cast<__nv_bfloat162*>(g_Wh + o)     = __nv_bfloat162{h0, h1};
            *reinterpret_cast<__nv_bfloat162*>(g_Wh + o + 2) = __nv_bfloat162{h2, h3};
            *reinterpret_cast<__nv_bfloat162*>(g_Wl + o)     = __nv_bfloat162{l0, l1};
            *reinterpret_cast<__nv_bfloat162*>(g_Wl + o + 2) = __nv_bfloat162{l2, l3};
        }
        return;
    }
    const int b = blockIdx.y;
    const int j0 = blockIdx.x * 4;
    const int npad = g_npad[b];
    if (j0 >= npad) return;
    const int cnt = g_cnt[b];

    #pragma unroll
    for (int r = 0; r < 4; ++r) {
        const int j = j0 + r;
        if (j >= npad) break;
        const size_t o = ((size_t)b * S_DIM + j) * H_DIM + col;
        if (j < cnt) {
            const int s = g_idx[b * S_DIM + j];
            float4 v = *reinterpret_cast<const float4*>(
                X + ((size_t)b * S_DIM + s) * H_DIM + col);
            __nv_bfloat16 h0, l0, h1, l1, h2, l2, h3, l3;
            split2(v.x, h0, l0); split2(v.y, h1, l1); split2(v.z, h2, l2); split2(v.w, h3, l3);
            *reinterpret_cast<__nv_bfloat162*>(g_Xh + o)     = __nv_bfloat162{h0, h1};
            *reinterpret_cast<__nv_bfloat162*>(g_Xh + o + 2) = __nv_bfloat162{h2, h3};
            *reinterpret_cast<__nv_bfloat162*>(g_Xl + o)     = __nv_bfloat162{l0, l1};
            *reinterpret_cast<__nv_bfloat162*>(g_Xl + o + 2) = __nv_bfloat162{l2, l3};
        } else {
            *reinterpret_cast<uint2*>(g_Xh + o) = make_uint2(0, 0);
            *reinterpret_cast<uint2*>(g_Xl + o) = make_uint2(0, 0);
        }
    }
}

// ---------------------------------------------------------------------------
// bf16x3 split GEMM via mma.sync. CTA 128(M) x 64(N), K-chunk 64, 8 warps
// (4M x 2N), warp tile 32x32. 2-stage cp.async pipeline, one barrier per
// chunk, 2 CTAs/SM.
//   NK > 0: compile-time trip count (GEMM1: 16)
//   NK == 0: dynamic nk = g_npad[b]/64 (GEMM2)
// ---------------------------------------------------------------------------
#define STAGE_BYTES 49152
#define GEMM_SMEM   (2 * STAGE_BYTES)

template <bool B_KMAJOR, bool N_LIM, int NK>
__global__ void __launch_bounds__(256, 2) gemm_hmma_x3(
    const __nv_bfloat16* __restrict__ Ah, const __nv_bfloat16* __restrict__ Al,
    const __nv_bfloat16* __restrict__ Bh, const __nv_bfloat16* __restrict__ Bl,
    float* __restrict__ D,
    int lda, int ldb, int ldd,
    size_t strideA, size_t strideB, size_t strideD)
{
    extern __shared__ char smem[];
    const uint32_t sb = smem_u32(smem);
    const int tid = threadIdx.x;
    const int wid = tid >> 5, lane = tid & 31;
    const int warp_m = wid & 3, warp_n = wid >> 2;
    const int b  = blockIdx.z;
    const int m0 = blockIdx.y * 128;
    const int n0 = blockIdx.x * 64;

    if (N_LIM && n0 >= g_npad[b]) return;
    const int nk = (NK > 0) ? NK : (g_npad[b] >> 6);

    const __nv_bfloat16* tAh = Ah + (size_t)b * strideA + (size_t)m0 * lda;
    const __nv_bfloat16* tAl = Al + (size_t)b * strideA + (size_t)m0 * lda;
    const __nv_bfloat16* pBh = Bh + (size_t)b * strideB;
    const __nv_bfloat16* pBl = Bl + (size_t)b * strideB;

    float acc[2][4][4];
    #pragma unroll
    for (int i = 0; i < 2; ++i)
        #pragma unroll
        for (int j = 0; j < 4; ++j)
            #pragma unroll
            for (int q = 0; q < 4; ++q) acc[i][j][q] = 0.0f;

    auto load_stage = [&](int c, int st) {
        const uint32_t base = sb + st * STAGE_BYTES;
        #pragma unroll
        for (int i = 0; i < 4; ++i) {
            int idx = i * 256 + tid;
            int row = idx >> 3, sl = idx & 7;
            uint32_t doff = SWZ128(row * 128 + sl * 16);
            CP_ASYNC16(base + doff,         tAh + (size_t)row * lda + c * 64 + sl * 8);
            CP_ASYNC16(base + 16384 + doff, tAl + (size_t)row * lda + c * 64 + sl * 8);
        }
        #pragma unroll
        for (int i = 0; i < 2; ++i) {
            int idx = i * 256 + tid;
            int row = idx >> 3, sl = idx & 7;
            uint32_t doff = SWZ128(row * 128 + sl * 16);
            if (B_KMAJOR) {
                CP_ASYNC16(base + 32768 + doff, pBh + (size_t)(n0 + row) * ldb + c * 64 + sl * 8);
                CP_ASYNC16(base + 40960 + doff, pBl + (size_t)(n0 + row) * ldb + c * 64 + sl * 8);
            } else {
                CP_ASYNC16(base + 32768 + doff, pBh + (size_t)(c * 64 + row) * ldb + n0 + sl * 8);
                CP_ASYNC16(base + 40960 + doff, pBl + (size_t)(c * 64 + row) * ldb + n0 + sl * 8);
            }
        }
        CP_COMMIT();
    };

    load_stage(0, 0);

    for (int c = 0; c < nk; ++c) {
        CP_WAIT0();
        __syncthreads();
        if (c + 1 < nk) load_stage(c + 1, (c + 1) & 1);

        const uint32_t base = sb + (c & 1) * STAGE_BYTES;
        const uint32_t sAh = base, sAl = base + 16384;
        const uint32_t sBh = base + 32768, sBl = base + 40960;

        #pragma unroll
        for (int ks = 0; ks < 4; ++ks) {
            uint32_t ah[2][4], bh[4][2];
            #pragma unroll
            for (int mt = 0; mt < 2; ++mt) {
                int row = warp_m * 32 + mt * 16 + (lane & 15);
                uint32_t off = SWZ128(row * 128 + ks * 32 + ((lane >> 4) << 4));
                LDSM_X4(ah[mt][0], ah[mt][1], ah[mt][2], ah[mt][3], sAh + off);
            }
            #pragma unroll
            for (int nt2 = 0; nt2 < 2; ++nt2) {
                if (B_KMAJOR) {
                    int row = warp_n * 32 + nt2 * 16 + ((lane >> 4) << 3) + (lane & 7);
                    uint32_t off = SWZ128(row * 128 + ks * 32 + (((lane >> 3) & 1) << 4));
                    LDSM_X4(bh[2 * nt2][0], bh[2 * nt2][1], bh[2 * nt2 + 1][0], bh[2 * nt2 + 1][1], sBh + off);
                } else {
                    int krow = ks * 16 + (((lane >> 3) & 1) << 3) + (lane & 7);
                    int col  = warp_n * 32 + nt2 * 16 + ((lane >> 4) << 3);
                    uint32_t off = SWZ128(krow * 128 + col * 2);
                    LDSM_X4T(bh[2 * nt2][0], bh[2 * nt2][1], bh[2 * nt2 + 1][0], bh[2 * nt2 + 1][1], sBh + off);
                }
            }
            #pragma unroll
            for (int mt = 0; mt < 2; ++mt)
                #pragma unroll
                for (int nt = 0; nt < 4; ++nt)
                    MMA_BF16(acc[mt][nt], ah[mt][0], ah[mt][1], ah[mt][2], ah[mt][3], bh[nt][0], bh[nt][1]);

            uint32_t al[2][4], bl[4][2];
            #pragma unroll
            for (int mt = 0; mt < 2; ++mt) {
                int row = warp_m * 32 + mt * 16 + (lane & 15);
                uint32_t off = SWZ128(row * 128 + ks * 32 + ((lane >> 4) << 4));
                LDSM_X4(al[mt][0], al[mt][1], al[mt][2], al[mt][3], sAl + off);
            }
            #pragma unroll
            for (int nt2 = 0; nt2 < 2; ++nt2) {
                if (B_KMAJOR) {
                    int row = warp_n * 32 + nt2 * 16 + ((lane >> 4) << 3) + (lane & 7);
                    uint32_t off = SWZ128(row * 128 + ks * 32 + (((lane >> 3) & 1) << 4));
                    LDSM_X4(bl[2 * nt2][0], bl[2 * nt2][1], bl[2 * nt2 + 1][0], bl[2 * nt2 + 1][1], sBl + off);
                } else {
                    int krow = ks * 16 + (((lane >> 3) & 1) << 3) + (lane & 7);
                    int col  = warp_n * 32 + nt2 * 16 + ((lane >> 4) << 3);
                    uint32_t off = SWZ128(krow * 128 + col * 2);
                    LDSM_X4T(bl[2 * nt2][0], bl[2 * nt2][1], bl[2 * nt2 + 1][0], bl[2 * nt2 + 1][1], sBl + off);
                }
            }
            #pragma unroll
            for (int mt = 0; mt < 2; ++mt)
                #pragma unroll
                for (int nt = 0; nt < 4; ++nt) {
                    MMA_BF16(acc[mt][nt], ah[mt][0], ah[mt][1], ah[mt][2], ah[mt][3], bl[nt][0], bl[nt][1]);
                    MMA_BF16(acc[mt][nt], al[mt][0], al[mt][1], al[mt][2], al[mt][3], bh[nt][0], bh[nt][1]);
                }
        }
    }

    float* Db = D + (size_t)b * strideD;
    #pragma unroll
    for (int mt = 0; mt < 2; ++mt) {
        int row = m0 + warp_m * 32 + mt * 16 + (lane >> 2);
        #pragma unroll
        for (int nt = 0; nt < 4; ++nt) {
            int col = n0 + warp_n * 32 + nt * 8 + (lane & 3) * 2;
            *reinterpret_cast<float2*>(Db + (size_t)row * ldd + col) =
                make_float2(acc[mt][nt][0], acc[mt][nt][1]);
            *reinterpret_cast<float2*>(Db + (size_t)(row + 8) * ldd + col) =
                make_float2(acc[mt][nt][2], acc[mt][nt][3]);
        }
    }
}

// ---------------------------------------------------------------------------
// Softmax over compacted columns j < cnt; skips 128-col chunks >= npad.
// __expf: fast exp, error ~1e-6 relative — invisible at rel_err 2.8e-5.
// ---------------------------------------------------------------------------
__global__ void __launch_bounds__(256) softmax_split()
{
    const int row  = blockIdx.x * 8 + (threadIdx.x >> 5);
    const int lane = threadIdx.x & 31;
    const int b    = row >> 9;
    const int cnt  = g_cnt[b];
    const int npad = g_npad[b];

    const float* p = g_scores + (size_t)row * S_DIM;

    float4 fv[4];
    float mx = -3e38f;
    #pragma unroll
    for (int c = 0; c < 4; ++c) {
        if (c * 128 < npad) {
            const int s = c * 128 + lane * 4;
            float4 x = *reinterpret_cast<const float4*>(p + s);
            x.x = (s + 0 < cnt) ? x.x : NEG_INF_F;
            x.y = (s + 1 < cnt) ? x.y : NEG_INF_F;
            x.z = (s + 2 < cnt) ? x.z : NEG_INF_F;
            x.w = (s + 3 < cnt) ? x.w : NEG_INF_F;
            fv[c] = x;
            mx = fmaxf(mx, fmaxf(fmaxf(x.x, x.y), fmaxf(x.z, x.w)));
        } else {
            fv[c] = make_float4(NEG_INF_F, NEG_INF_F, NEG_INF_F, NEG_INF_F);
        }
    }
    #pragma unroll
    for (int o = 16; o > 0; o >>= 1) mx = fmaxf(mx, __shfl_xor_sync(0xffffffffu, mx, o));

    float sum = 0.0f;
    #pragma unroll
    for (int c = 0; c < 4; ++c) {
        if (c * 128 < npad) {
            fv[c].x = __expf(fv[c].x - mx); fv[c].y = __expf(fv[c].y - mx);
            fv[c].z = __expf(fv[c].z - mx); fv[c].w = __expf(fv[c].w - mx);
            sum += fv[c].x + fv[c].y + fv[c].z + fv[c].w;
        }
    }
    #pragma unroll
    for (int o = 16; o > 0; o >>= 1) sum += __shfl_xor_sync(0xffffffffu, sum, o);

    const float inv = 1.0f / sum;
    #pragma unroll
    for (int c = 0; c < 4; ++c) {
        if (c * 128 < npad) {
            const int s = c * 128 + lane * 4;
            float v0 = fv[c].x * inv, v1 = fv[c].y * inv, v2 = fv[c].z * inv, v3 = fv[c].w * inv;
            __nv_bfloat16 h0, l0, h1, l1, h2, l2, h3, l3;
            split2(v0, h0, l0); split2(v1, h1, l1); split2(v2, h2, l2); split2(v3, h3, l3);
            __nv_bfloat162* ph = reinterpret_cast<__nv_bfloat162*>(g_Ph + (size_t)row * S_DIM + s);
            __nv_bfloat162* pl = reinterpret_cast<__nv_bfloat162*>(g_Pl + (size_t)row * S_DIM + s);
            ph[0] = __nv_bfloat162{h0, h1}; ph[1] = __nv_bfloat162{h2, h3};
            pl[0] = __nv_bfloat162{l0, l1}; pl[1] = __nv_bfloat162{l2, l3};
        }
    }
}

// ---------------------------------------------------------------------------
// Launch
// ---------------------------------------------------------------------------
extern "C" void kernel_launch(void* const* d_in, const int* in_sizes, int n_in,
                              void* d_out, int out_size)
{
    const float* X    = (const float*)d_in[0];   // [B, S, H]
    const int*   mask = (const int*)  d_in[1];   // [B, S]
    const float* W    = (const float*)d_in[2];   // [L, H]
    float* out = (float*)d_out;                  // [B, L, H]

    cudaFuncSetAttribute(gemm_hmma_x3<true, true, 16>,
                         cudaFuncAttributeMaxDynamicSharedMemorySize, GEMM_SMEM);
    cudaFuncSetAttribute(gemm_hmma_x3<false, false, 0>,
                         cudaFuncAttributeMaxDynamicSharedMemorySize, GEMM_SMEM);

    void *pXh, *pXl, *pWh, *pWl, *pPh, *pPl, *pSc;
    cudaGetSymbolAddress(&pXh, g_Xh); cudaGetSymbolAddress(&pXl, g_Xl);
    cudaGetSymbolAddress(&pWh, g_Wh); cudaGetSymbolAddress(&pWl, g_Wl);
    cudaGetSymbolAddress(&pPh, g_Ph); cudaGetSymbolAddress(&pPl, g_Pl);
    cudaGetSymbolAddress(&pSc, g_scores);

    compact_mask<<<B_DIM, 512>>>(mask);
    gather_convert<<<dim3(S_DIM / 4, B_DIM + 1), 256>>>(X, W);

    // GEMM1 (NT, compacted N, NK=16): scores[b,l,j] = W[l,:] . Xc[b,j,:]
    gemm_hmma_x3<true, true, 16><<<dim3(S_DIM / 64, L_DIM / 128, B_DIM), 256, GEMM_SMEM>>>(
        (const __nv_bfloat16*)pWh, (const __nv_bfloat16*)pWl,
        (const __nv_bfloat16*)pXh, (const __nv_bfloat16*)pXl,
        (float*)pSc,
        H_DIM, H_DIM, S_DIM,
        0, (size_t)S_DIM * H_DIM, (size_t)L_DIM * S_DIM);

    softmax_split<<<(B_DIM * L_DIM) / 8, 256>>>();

    // GEMM2 (NN, compacted K): out[b,l,h] = Pc[b,l,:] . Xc[b,:,h]
    gemm_hmma_x3<false, false, 0><<<dim3(H_DIM / 64, L_DIM / 128, B_DIM), 256, GEMM_SMEM>>>(
        (const __nv_bfloat16*)pPh, (const __nv_bfloat16*)pPl,
        (const __nv_bfloat16*)pXh, (const __nv_bfloat16*)pXl,
        out,
        S_DIM, H_DIM, H_DIM,
        (size_t)L_DIM * S_DIM, (size_t)S_DIM * H_DIM, (size_t)L_DIM * H_DIM);
}

// round 15
// speedup vs baseline: 1.5019x; 1.0058x over previous
#include <cuda_runtime.h>
#include <cuda_bf16.h>
#include <stdint.h>

#define B_DIM 64
#define S_DIM 512
#define H_DIM 1024
#define L_DIM 512
#define NEG_INF_F (-1e9f)

// ---------------------------------------------------------------------------
// Scratch (module-load allocations, allowed)
// ---------------------------------------------------------------------------
__device__ float         g_scores[(size_t)B_DIM * L_DIM * S_DIM];
__device__ __nv_bfloat16 g_Xh[(size_t)B_DIM * S_DIM * H_DIM];      // compacted
__device__ __nv_bfloat16 g_Xl[(size_t)B_DIM * S_DIM * H_DIM];
__device__ __nv_bfloat16 g_Wh[(size_t)L_DIM * H_DIM];
__device__ __nv_bfloat16 g_Wl[(size_t)L_DIM * H_DIM];
__device__ __nv_bfloat16 g_Ph[(size_t)B_DIM * L_DIM * S_DIM];      // compacted K
__device__ __nv_bfloat16 g_Pl[(size_t)B_DIM * L_DIM * S_DIM];
__device__ int g_idx[B_DIM * S_DIM];
__device__ int g_cnt[B_DIM];
__device__ int g_npad[B_DIM];          // cnt rounded up to 64

// ---------------------------------------------------------------------------
// Helpers
// ---------------------------------------------------------------------------
__device__ __forceinline__ uint32_t smem_u32(const void* p) {
    uint32_t a;
    asm("{ .reg .u64 t; cvta.to.shared.u64 t, %1; cvt.u32.u64 %0, t; }" : "=r"(a) : "l"(p));
    return a;
}

#define CP_ASYNC16(dst, src) \
    asm volatile("cp.async.cg.shared.global [%0], [%1], 16;" :: "r"(dst), "l"(src))
#define CP_COMMIT()  asm volatile("cp.async.commit_group;" ::: "memory")
#define CP_WAIT0()   asm volatile("cp.async.wait_group 0;" ::: "memory")

#define LDSM_X4(r0, r1, r2, r3, a) \
    asm volatile("ldmatrix.sync.aligned.m8n8.x4.shared.b16 {%0,%1,%2,%3}, [%4];" \
        : "=r"(r0), "=r"(r1), "=r"(r2), "=r"(r3) : "r"(a))
#define LDSM_X4T(r0, r1, r2, r3, a) \
    asm volatile("ldmatrix.sync.aligned.m8n8.x4.trans.shared.b16 {%0,%1,%2,%3}, [%4];" \
        : "=r"(r0), "=r"(r1), "=r"(r2), "=r"(r3) : "r"(a))

#define MMA_BF16(d, a0, a1, a2, a3, b0, b1) \
    asm volatile("mma.sync.aligned.m16n8k16.row.col.f32.bf16.bf16.f32 " \
        "{%0,%1,%2,%3},{%4,%5,%6,%7},{%8,%9},{%0,%1,%2,%3};" \
        : "+f"((d)[0]), "+f"((d)[1]), "+f"((d)[2]), "+f"((d)[3]) \
        : "r"(a0), "r"(a1), "r"(a2), "r"(a3), "r"(b0), "r"(b1))

#define SWZ128(o) ((o) ^ (((o) >> 3) & 0x70))

__device__ __forceinline__ void split2(float v, __nv_bfloat16& h, __nv_bfloat16& l) {
    h = __float2bfloat16(v);
    l = __float2bfloat16(v - __bfloat162float(h));
}

// ---------------------------------------------------------------------------
// Mask compaction: one block of 512 threads per batch.
// ---------------------------------------------------------------------------
__global__ void __launch_bounds__(512) compact_mask(const int* __restrict__ mask) {
    const int b = blockIdx.x, tid = threadIdx.x;
    const int lane = tid & 31, w = tid >> 5;
    const int m = (mask[(size_t)b * S_DIM + tid] != 0);
    const unsigned bal = __ballot_sync(0xffffffffu, m);

    __shared__ int ws[16], woff[16];
    if (lane == 0) ws[w] = __popc(bal);
    __syncthreads();
    if (tid == 0) {
        int s = 0;
        #pragma unroll
        for (int i = 0; i < 16; ++i) { woff[i] = s; s += ws[i]; }
        g_cnt[b]  = s;
        int np = ((s + 63) >> 6) << 6;
        g_npad[b] = (np < 64) ? 64 : np;
    }
    __syncthreads();
    if (m) {
        int pos = woff[w] + __popc(bal & ((1u << lane) - 1u));
        g_idx[b * S_DIM + pos] = tid;
    }
}

// ---------------------------------------------------------------------------
// Gather + split-convert X (4 rows/block), and convert W on the extra y-slice.
// X reads are read-once -> __ldcs (keep L2 for GEMM tiles).
// ---------------------------------------------------------------------------
__global__ void __launch_bounds__(256) gather_convert(const float* __restrict__ X,
                                                      const float* __restrict__ W) {
    const int col = threadIdx.x * 4;
    if (blockIdx.y == B_DIM) {
        const int r0 = blockIdx.x * 4;
        #pragma unroll
        for (int r = 0; r < 4; ++r) {
            const size_t o = (size_t)(r0 + r) * H_DIM + col;
            float4 v = __ldcs(reinterpret_cast<const float4*>(W + o));
            __nv_bfloat16 h0, l0, h1, l1, h2, l2, h3, l3;
            split2(v.x, h0, l0); split2(v.y, h1, l1); split2(v.z, h2, l2); split2(v.w, h3, l3);
            *reinterpret_cast<__nv_bfloat162*>(g_Wh + o)     = __nv_bfloat162{h0, h1};
            *reinterpret_cast<__nv_bfloat162*>(g_Wh + o + 2) = __nv_bfloat162{h2, h3};
            *reinterpret_cast<__nv_bfloat162*>(g_Wl + o)     = __nv_bfloat162{l0, l1};
            *reinterpret_cast<__nv_bfloat162*>(g_Wl + o + 2) = __nv_bfloat162{l2, l3};
        }
        return;
    }
    const int b = blockIdx.y;
    const int j0 = blockIdx.x * 4;
    const int npad = g_npad[b];
    if (j0 >= npad) return;
    const int cnt = g_cnt[b];

    #pragma unroll
    for (int r = 0; r < 4; ++r) {
        const int j = j0 + r;
        if (j >= npad) break;
        const size_t o = ((size_t)b * S_DIM + j) * H_DIM + col;
        if (j < cnt) {
            const int s = g_idx[b * S_DIM + j];
            float4 v = __ldcs(reinterpret_cast<const float4*>(
                X + ((size_t)b * S_DIM + s) * H_DIM + col));
            __nv_bfloat16 h0, l0, h1, l1, h2, l2, h3, l3;
            split2(v.x, h0, l0); split2(v.y, h1, l1); split2(v.z, h2, l2); split2(v.w, h3, l3);
            *reinterpret_cast<__nv_bfloat162*>(g_Xh + o)     = __nv_bfloat162{h0, h1};
            *reinterpret_cast<__nv_bfloat162*>(g_Xh + o + 2) = __nv_bfloat162{h2, h3};
            *reinterpret_cast<__nv_bfloat162*>(g_Xl + o)     = __nv_bfloat162{l0, l1};
            *reinterpret_cast<__nv_bfloat162*>(g_Xl + o + 2) = __nv_bfloat162{l2, l3};
        } else {
            *reinterpret_cast<uint2*>(g_Xh + o) = make_uint2(0, 0);
            *reinterpret_cast<uint2*>(g_Xl + o) = make_uint2(0, 0);
        }
    }
}

// ---------------------------------------------------------------------------
// bf16x3 split GEMM via mma.sync. CTA 128(M) x 64(N), K-chunk 64, 8 warps
// (4M x 2N), warp tile 32x32. 2-stage cp.async pipeline, one barrier per
// chunk, 2 CTAs/SM. Inner slice fully software-pipelined:
//   LDSM(ah,bh) -> MMA hh -> LDSM(al) -> MMA al*bh -> LDSM(bl) -> MMA ah*bl
//   NK > 0: compile-time trip count (GEMM1: 16)
//   NK == 0: dynamic nk = g_npad[b]/64 (GEMM2)
// ---------------------------------------------------------------------------
#define STAGE_BYTES 49152
#define GEMM_SMEM   (2 * STAGE_BYTES)

template <bool B_KMAJOR, bool N_LIM, int NK>
__global__ void __launch_bounds__(256, 2) gemm_hmma_x3(
    const __nv_bfloat16* __restrict__ Ah, const __nv_bfloat16* __restrict__ Al,
    const __nv_bfloat16* __restrict__ Bh, const __nv_bfloat16* __restrict__ Bl,
    float* __restrict__ D,
    int lda, int ldb, int ldd,
    size_t strideA, size_t strideB, size_t strideD)
{
    extern __shared__ char smem[];
    const uint32_t sb = smem_u32(smem);
    const int tid = threadIdx.x;
    const int wid = tid >> 5, lane = tid & 31;
    const int warp_m = wid & 3, warp_n = wid >> 2;
    const int b  = blockIdx.z;
    const int m0 = blockIdx.y * 128;
    const int n0 = blockIdx.x * 64;

    if (N_LIM && n0 >= g_npad[b]) return;
    const int nk = (NK > 0) ? NK : (g_npad[b] >> 6);

    const __nv_bfloat16* tAh = Ah + (size_t)b * strideA + (size_t)m0 * lda;
    const __nv_bfloat16* tAl = Al + (size_t)b * strideA + (size_t)m0 * lda;
    const __nv_bfloat16* pBh = Bh + (size_t)b * strideB;
    const __nv_bfloat16* pBl = Bl + (size_t)b * strideB;

    float acc[2][4][4];
    #pragma unroll
    for (int i = 0; i < 2; ++i)
        #pragma unroll
        for (int j = 0; j < 4; ++j)
            #pragma unroll
            for (int q = 0; q < 4; ++q) acc[i][j][q] = 0.0f;

    auto load_stage = [&](int c, int st) {
        const uint32_t base = sb + st * STAGE_BYTES;
        #pragma unroll
        for (int i = 0; i < 4; ++i) {
            int idx = i * 256 + tid;
            int row = idx >> 3, sl = idx & 7;
            uint32_t doff = SWZ128(row * 128 + sl * 16);
            CP_ASYNC16(base + doff,         tAh + (size_t)row * lda + c * 64 + sl * 8);
            CP_ASYNC16(base + 16384 + doff, tAl + (size_t)row * lda + c * 64 + sl * 8);
        }
        #pragma unroll
        for (int i = 0; i < 2; ++i) {
            int idx = i * 256 + tid;
            int row = idx >> 3, sl = idx & 7;
            uint32_t doff = SWZ128(row * 128 + sl * 16);
            if (B_KMAJOR) {
                CP_ASYNC16(base + 32768 + doff, pBh + (size_t)(n0 + row) * ldb + c * 64 + sl * 8);
                CP_ASYNC16(base + 40960 + doff, pBl + (size_t)(n0 + row) * ldb + c * 64 + sl * 8);
            } else {
                CP_ASYNC16(base + 32768 + doff, pBh + (size_t)(c * 64 + row) * ldb + n0 + sl * 8);
                CP_ASYNC16(base + 40960 + doff, pBl + (size_t)(c * 64 + row) * ldb + n0 + sl * 8);
            }
        }
        CP_COMMIT();
    };

    load_stage(0, 0);

    for (int c = 0; c < nk; ++c) {
        CP_WAIT0();
        __syncthreads();
        if (c + 1 < nk) load_stage(c + 1, (c + 1) & 1);

        const uint32_t base = sb + (c & 1) * STAGE_BYTES;
        const uint32_t sAh = base, sAl = base + 16384;
        const uint32_t sBh = base + 32768, sBl = base + 40960;

        #pragma unroll
        for (int ks = 0; ks < 4; ++ks) {
            // --- stage 1: hi fragments, hh product ---
            uint32_t ah[2][4], bh[4][2];
            #pragma unroll
            for (int mt = 0; mt < 2; ++mt) {
                int row = warp_m * 32 + mt * 16 + (lane & 15);
                uint32_t off = SWZ128(row * 128 + ks * 32 + ((lane >> 4) << 4));
                LDSM_X4(ah[mt][0], ah[mt][1], ah[mt][2], ah[mt][3], sAh + off);
            }
            #pragma unroll
            for (int nt2 = 0; nt2 < 2; ++nt2) {
                if (B_KMAJOR) {
                    int row = warp_n * 32 + nt2 * 16 + ((lane >> 4) << 3) + (lane & 7);
                    uint32_t off = SWZ128(row * 128 + ks * 32 + (((lane >> 3) & 1) << 4));
                    LDSM_X4(bh[2 * nt2][0], bh[2 * nt2][1], bh[2 * nt2 + 1][0], bh[2 * nt2 + 1][1], sBh + off);
                } else {
                    int krow = ks * 16 + (((lane >> 3) & 1) << 3) + (lane & 7);
                    int col  = warp_n * 32 + nt2 * 16 + ((lane >> 4) << 3);
                    uint32_t off = SWZ128(krow * 128 + col * 2);
                    LDSM_X4T(bh[2 * nt2][0], bh[2 * nt2][1], bh[2 * nt2 + 1][0], bh[2 * nt2 + 1][1], sBh + off);
                }
            }
            #pragma unroll
            for (int mt = 0; mt < 2; ++mt)
                #pragma unroll
                for (int nt = 0; nt < 4; ++nt)
                    MMA_BF16(acc[mt][nt], ah[mt][0], ah[mt][1], ah[mt][2], ah[mt][3], bh[nt][0], bh[nt][1]);

            // --- stage 2: al fragments, al*bh product (hides al LDSM) ---
            uint32_t al[2][4];
            #pragma unroll
            for (int mt = 0; mt < 2; ++mt) {
                int row = warp_m * 32 + mt * 16 + (lane & 15);
                uint32_t off = SWZ128(row * 128 + ks * 32 + ((lane >> 4) << 4));
                LDSM_X4(al[mt][0], al[mt][1], al[mt][2], al[mt][3], sAl + off);
            }
            #pragma unroll
            for (int mt = 0; mt < 2; ++mt)
                #pragma unroll
                for (int nt = 0; nt < 4; ++nt)
                    MMA_BF16(acc[mt][nt], al[mt][0], al[mt][1], al[mt][2], al[mt][3], bh[nt][0], bh[nt][1]);

            // --- stage 3: bl fragments, ah*bl product (hides bl LDSM) ---
            uint32_t bl[4][2];
            #pragma unroll
            for (int nt2 = 0; nt2 < 2; ++nt2) {
                if (B_KMAJOR) {
                    int row = warp_n * 32 + nt2 * 16 + ((lane >> 4) << 3) + (lane & 7);
                    uint32_t off = SWZ128(row * 128 + ks * 32 + (((lane >> 3) & 1) << 4));
                    LDSM_X4(bl[2 * nt2][0], bl[2 * nt2][1], bl[2 * nt2 + 1][0], bl[2 * nt2 + 1][1], sBl + off);
                } else {
                    int krow = ks * 16 + (((lane >> 3) & 1) << 3) + (lane & 7);
                    int col  = warp_n * 32 + nt2 * 16 + ((lane >> 4) << 3);
                    uint32_t off = SWZ128(krow * 128 + col * 2);
                    LDSM_X4T(bl[2 * nt2][0], bl[2 * nt2][1], bl[2 * nt2 + 1][0], bl[2 * nt2 + 1][1], sBl + off);
                }
            }
            #pragma unroll
            for (int mt = 0; mt < 2; ++mt)
                #pragma unroll
                for (int nt = 0; nt < 4; ++nt)
                    MMA_BF16(acc[mt][nt], ah[mt][0], ah[mt][1], ah[mt][2], ah[mt][3], bl[nt][0], bl[nt][1]);
        }
    }

    float* Db = D + (size_t)b * strideD;
    #pragma unroll
    for (int mt = 0; mt < 2; ++mt) {
        int row = m0 + warp_m * 32 + mt * 16 + (lane >> 2);
        #pragma unroll
        for (int nt = 0; nt < 4; ++nt) {
            int col = n0 + warp_n * 32 + nt * 8 + (lane & 3) * 2;
            *reinterpret_cast<float2*>(Db + (size_t)row * ldd + col) =
                make_float2(acc[mt][nt][0], acc[mt][nt][1]);
            *reinterpret_cast<float2*>(Db + (size_t)(row + 8) * ldd + col) =
                make_float2(acc[mt][nt][2], acc[mt][nt][3]);
        }
    }
}

// ---------------------------------------------------------------------------
// Softmax over compacted columns j < cnt; skips 128-col chunks >= npad.
// Scores are read-once -> __ldcs. __expf: error ~1e-6 rel, invisible here.
// ---------------------------------------------------------------------------
__global__ void __launch_bounds__(256) softmax_split()
{
    const int row  = blockIdx.x * 8 + (threadIdx.x >> 5);
    const int lane = threadIdx.x & 31;
    const int b    = row >> 9;
    const int cnt  = g_cnt[b];
    const int npad = g_npad[b];

    const float* p = g_scores + (size_t)row * S_DIM;

    float4 fv[4];
    float mx = -3e38f;
    #pragma unroll
    for (int c = 0; c < 4; ++c) {
        if (c * 128 < npad) {
            const int s = c * 128 + lane * 4;
            float4 x = __ldcs(reinterpret_cast<const float4*>(p + s));
            x.x = (s + 0 < cnt) ? x.x : NEG_INF_F;
            x.y = (s + 1 < cnt) ? x.y : NEG_INF_F;
            x.z = (s + 2 < cnt) ? x.z : NEG_INF_F;
            x.w = (s + 3 < cnt) ? x.w : NEG_INF_F;
            fv[c] = x;
            mx = fmaxf(mx, fmaxf(fmaxf(x.x, x.y), fmaxf(x.z, x.w)));
        } else {
            fv[c] = make_float4(NEG_INF_F, NEG_INF_F, NEG_INF_F, NEG_INF_F);
        }
    }
    #pragma unroll
    for (int o = 16; o > 0; o >>= 1) mx = fmaxf(mx, __shfl_xor_sync(0xffffffffu, mx, o));

    float sum = 0.0f;
    #pragma unroll
    for (int c = 0; c < 4; ++c) {
        if (c * 128 < npad) {
            fv[c].x = __expf(fv[c].x - mx); fv[c].y = __expf(fv[c].y - mx);
            fv[c].z = __expf(fv[c].z - mx); fv[c].w = __expf(fv[c].w - mx);
            sum += fv[c].x + fv[c].y + fv[c].z + fv[c].w;
        }
    }
    #pragma unroll
    for (int o = 16; o > 0; o >>= 1) sum += __shfl_xor_sync(0xffffffffu, sum, o);

    const float inv = 1.0f / sum;
    #pragma unroll
    for (int c = 0; c < 4; ++c) {
        if (c * 128 < npad) {
            const int s = c * 128 + lane * 4;
            float v0 = fv[c].x * inv, v1 = fv[c].y * inv, v2 = fv[c].z * inv, v3 = fv[c].w * inv;
            __nv_bfloat16 h0, l0, h1, l1, h2, l2, h3, l3;
            split2(v0, h0, l0); split2(v1, h1, l1); split2(v2, h2, l2); split2(v3, h3, l3);
            __nv_bfloat162* ph = reinterpret_cast<__nv_bfloat162*>(g_Ph + (size_t)row * S_DIM + s);
            __nv_bfloat162* pl = reinterpret_cast<__nv_bfloat162*>(g_Pl + (size_t)row * S_DIM + s);
            ph[0] = __nv_bfloat162{h0, h1}; ph[1] = __nv_bfloat162{h2, h3};
            pl[0] = __nv_bfloat162{l0, l1}; pl[1] = __nv_bfloat162{l2, l3};
        }
    }
}

// ---------------------------------------------------------------------------
// Launch
// ---------------------------------------------------------------------------
extern "C" void kernel_launch(void* const* d_in, const int* in_sizes, int n_in,
                              void* d_out, int out_size)
{
    const float* X    = (const float*)d_in[0];   // [B, S, H]
    const int*   mask = (const int*)  d_in[1];   // [B, S]
    const float* W    = (const float*)d_in[2];   // [L, H]
    float* out = (float*)d_out;                  // [B, L, H]

    cudaFuncSetAttribute(gemm_hmma_x3<true, true, 16>,
                         cudaFuncAttributeMaxDynamicSharedMemorySize, GEMM_SMEM);
    cudaFuncSetAttribute(gemm_hmma_x3<false, false, 0>,
                         cudaFuncAttributeMaxDynamicSharedMemorySize, GEMM_SMEM);

    void *pXh, *pXl, *pWh, *pWl, *pPh, *pPl, *pSc;
    cudaGetSymbolAddress(&pXh, g_Xh); cudaGetSymbolAddress(&pXl, g_Xl);
    cudaGetSymbolAddress(&pWh, g_Wh); cudaGetSymbolAddress(&pWl, g_Wl);
    cudaGetSymbolAddress(&pPh, g_Ph); cudaGetSymbolAddress(&pPl, g_Pl);
    cudaGetSymbolAddress(&pSc, g_scores);

    compact_mask<<<B_DIM, 512>>>(mask);
    gather_convert<<<dim3(S_DIM / 4, B_DIM + 1), 256>>>(X, W);

    // GEMM1 (NT, compacted N, NK=16): scores[b,l,j] = W[l,:] . Xc[b,j,:]
    gemm_hmma_x3<true, true, 16><<<dim3(S_DIM / 64, L_DIM / 128, B_DIM), 256, GEMM_SMEM>>>(
        (const __nv_bfloat16*)pWh, (const __nv_bfloat16*)pWl,
        (const __nv_bfloat16*)pXh, (const __nv_bfloat16*)pXl,
        (float*)pSc,
        H_DIM, H_DIM, S_DIM,
        0, (size_t)S_DIM * H_DIM, (size_t)L_DIM * S_DIM);

    softmax_split<<<(B_DIM * L_DIM) / 8, 256>>>();

    // GEMM2 (NN, compacted K): out[b,l,h] = Pc[b,l,:] . Xc[b,:,h]
    gemm_hmma_x3<false, false, 0><<<dim3(H_DIM / 64, L_DIM / 128, B_DIM), 256, GEMM_SMEM>>>(
        (const __nv_bfloat16*)pPh, (const __nv_bfloat16*)pPl,
        (const __nv_bfloat16*)pXh, (const __nv_bfloat16*)pXl,
        out,
        S_DIM, H_DIM, H_DIM,
        (size_t)L_DIM * S_DIM, (size_t)S_DIM * H_DIM, (size_t)L_DIM * H_DIM);
}

// round 16
// speedup vs baseline: 1.5031x; 1.0008x over previous
#include <cuda_runtime.h>
#include <cuda_bf16.h>
#include <stdint.h>

#define B_DIM 64
#define S_DIM 512
#define H_DIM 1024
#define L_DIM 512
#define NEG_INF_F (-1e9f)

// ---------------------------------------------------------------------------
// Scratch (module-load allocations, allowed)
// ---------------------------------------------------------------------------
__device__ float         g_scores[(size_t)B_DIM * L_DIM * S_DIM];
__device__ __nv_bfloat16 g_Xh[(size_t)B_DIM * S_DIM * H_DIM];      // compacted
__device__ __nv_bfloat16 g_Xl[(size_t)B_DIM * S_DIM * H_DIM];
__device__ __nv_bfloat16 g_Wh[(size_t)L_DIM * H_DIM];
__device__ __nv_bfloat16 g_Wl[(size_t)L_DIM * H_DIM];
__device__ __nv_bfloat16 g_Ph[(size_t)B_DIM * L_DIM * S_DIM];      // compacted K
__device__ __nv_bfloat16 g_Pl[(size_t)B_DIM * L_DIM * S_DIM];
__device__ int g_idx[B_DIM * S_DIM];
__device__ int g_cnt[B_DIM];
__device__ int g_npad[B_DIM];          // cnt rounded up to 64

// ---------------------------------------------------------------------------
// Helpers
// ---------------------------------------------------------------------------
__device__ __forceinline__ uint32_t smem_u32(const void* p) {
    uint32_t a;
    asm("{ .reg .u64 t; cvta.to.shared.u64 t, %1; cvt.u32.u64 %0, t; }" : "=r"(a) : "l"(p));
    return a;
}

#define CP_ASYNC16(dst, src) \
    asm volatile("cp.async.cg.shared.global [%0], [%1], 16;" :: "r"(dst), "l"(src))
#define CP_COMMIT()  asm volatile("cp.async.commit_group;" ::: "memory")
#define CP_WAIT0()   asm volatile("cp.async.wait_group 0;" ::: "memory")

#define LDSM_X4(r0, r1, r2, r3, a) \
    asm volatile("ldmatrix.sync.aligned.m8n8.x4.shared.b16 {%0,%1,%2,%3}, [%4];" \
        : "=r"(r0), "=r"(r1), "=r"(r2), "=r"(r3) : "r"(a))
#define LDSM_X4T(r0, r1, r2, r3, a) \
    asm volatile("ldmatrix.sync.aligned.m8n8.x4.trans.shared.b16 {%0,%1,%2,%3}, [%4];" \
        : "=r"(r0), "=r"(r1), "=r"(r2), "=r"(r3) : "r"(a))

#define MMA_BF16(d, a0, a1, a2, a3, b0, b1) \
    asm volatile("mma.sync.aligned.m16n8k16.row.col.f32.bf16.bf16.f32 " \
        "{%0,%1,%2,%3},{%4,%5,%6,%7},{%8,%9},{%0,%1,%2,%3};" \
        : "+f"((d)[0]), "+f"((d)[1]), "+f"((d)[2]), "+f"((d)[3]) \
        : "r"(a0), "r"(a1), "r"(a2), "r"(a3), "r"(b0), "r"(b1))

#define SWZ128(o) ((o) ^ (((o) >> 3) & 0x70))

__device__ __forceinline__ void split2(float v, __nv_bfloat16& h, __nv_bfloat16& l) {
    h = __float2bfloat16(v);
    l = __float2bfloat16(v - __bfloat162float(h));
}

// ---------------------------------------------------------------------------
// Mask compaction: one block of 512 threads per batch.
// ---------------------------------------------------------------------------
__global__ void __launch_bounds__(512) compact_mask(const int* __restrict__ mask) {
    const int b = blockIdx.x, tid = threadIdx.x;
    const int lane = tid & 31, w = tid >> 5;
    const int m = (mask[(size_t)b * S_DIM + tid] != 0);
    const unsigned bal = __ballot_sync(0xffffffffu, m);

    __shared__ int ws[16], woff[16];
    if (lane == 0) ws[w] = __popc(bal);
    __syncthreads();
    if (tid == 0) {
        int s = 0;
        #pragma unroll
        for (int i = 0; i < 16; ++i) { woff[i] = s; s += ws[i]; }
        g_cnt[b]  = s;
        int np = ((s + 63) >> 6) << 6;
        g_npad[b] = (np < 64) ? 64 : np;
    }
    __syncthreads();
    if (m) {
        int pos = woff[w] + __popc(bal & ((1u << lane) - 1u));
        g_idx[b * S_DIM + pos] = tid;
    }
}

// ---------------------------------------------------------------------------
// Gather + split-convert X (8 rows/block), and convert W on the extra y-slice.
// X reads are read-once -> __ldcs. Xh/Xl/Wh/Wl stay default-cached (GEMMs
// re-read them x4-8 from L2).
// ---------------------------------------------------------------------------
__global__ void __launch_bounds__(256) gather_convert(const float* __restrict__ X,
                                                      const float* __restrict__ W) {
    const int col = threadIdx.x * 4;
    if (blockIdx.y == B_DIM) {
        const int r0 = blockIdx.x * 8;
        #pragma unroll
        for (int r = 0; r < 8; ++r) {
            const size_t o = (size_t)(r0 + r) * H_DIM + col;
            float4 v = __ldcs(reinterpret_cast<const float4*>(W + o));
            __nv_bfloat16 h0, l0, h1, l1, h2, l2, h3, l3;
            split2(v.x, h0, l0); split2(v.y, h1, l1); split2(v.z, h2, l2); split2(v.w, h3, l3);
            *reinterpret_cast<__nv_bfloat162*>(g_Wh + o)     = __nv_bfloat162{h0, h1};
            *reinterpret_cast<__nv_bfloat162*>(g_Wh + o + 2) = __nv_bfloat162{h2, h3};
            *reinterpret_cast<__nv_bfloat162*>(g_Wl + o)     = __nv_bfloat162{l0, l1};
            *reinterpret_cast<__nv_bfloat162*>(g_Wl + o + 2) = __nv_bfloat162{l2, l3};
        }
        return;
    }
    const int b = blockIdx.y;
    const int j0 = blockIdx.x * 8;
    const int npad = g_npad[b];
    if (j0 >= npad) return;
    const int cnt = g_cnt[b];

    #pragma unroll
    for (int r = 0; r < 8; ++r) {
        const int j = j0 + r;
        if (j >= npad) break;
        const size_t o = ((size_t)b * S_DIM + j) * H_DIM + col;
        if (j < cnt) {
            const int s = g_idx[b * S_DIM + j];
            float4 v = __ldcs(reinterpret_cast<const float4*>(
                X + ((size_t)b * S_DIM + s) * H_DIM + col));
            __nv_bfloat16 h0, l0, h1, l1, h2, l2, h3, l3;
            split2(v.x, h0, l0); split2(v.y, h1, l1); split2(v.z, h2, l2); split2(v.w, h3, l3);
            *reinterpret_cast<__nv_bfloat162*>(g_Xh + o)     = __nv_bfloat162{h0, h1};
            *reinterpret_cast<__nv_bfloat162*>(g_Xh + o + 2) = __nv_bfloat162{h2, h3};
            *reinterpret_cast<__nv_bfloat162*>(g_Xl + o)     = __nv_bfloat162{l0, l1};
            *reinterpret_cast<__nv_bfloat162*>(g_Xl + o + 2) = __nv_bfloat162{l2, l3};
        } else {
            *reinterpret_cast<uint2*>(g_Xh + o) = make_uint2(0, 0);
            *reinterpret_cast<uint2*>(g_Xl + o) = make_uint2(0, 0);
        }
    }
}

// ---------------------------------------------------------------------------
// bf16x3 split GEMM via mma.sync. CTA 128(M) x 64(N), K-chunk 64, 8 warps
// (4M x 2N), warp tile 32x32. 2-stage cp.async pipeline, one barrier per
// chunk, 2 CTAs/SM. Inner slice software-pipelined:
//   LDSM(ah,bh) -> MMA hh -> LDSM(al) -> MMA al*bh -> LDSM(bl) -> MMA ah*bl
//   NK > 0: compile-time trip count (GEMM1: 16)
//   NK == 0: dynamic nk = g_npad[b]/64 (GEMM2)
//   STREAM_D: evict-first stores for write-once D (scores / out)
// ---------------------------------------------------------------------------
#define STAGE_BYTES 49152
#define GEMM_SMEM   (2 * STAGE_BYTES)

template <bool B_KMAJOR, bool N_LIM, int NK>
__global__ void __launch_bounds__(256, 2) gemm_hmma_x3(
    const __nv_bfloat16* __restrict__ Ah, const __nv_bfloat16* __restrict__ Al,
    const __nv_bfloat16* __restrict__ Bh, const __nv_bfloat16* __restrict__ Bl,
    float* __restrict__ D,
    int lda, int ldb, int ldd,
    size_t strideA, size_t strideB, size_t strideD)
{
    extern __shared__ char smem[];
    const uint32_t sb = smem_u32(smem);
    const int tid = threadIdx.x;
    const int wid = tid >> 5, lane = tid & 31;
    const int warp_m = wid & 3, warp_n = wid >> 2;
    const int b  = blockIdx.z;
    const int m0 = blockIdx.y * 128;
    const int n0 = blockIdx.x * 64;

    if (N_LIM && n0 >= g_npad[b]) return;
    const int nk = (NK > 0) ? NK : (g_npad[b] >> 6);

    const __nv_bfloat16* tAh = Ah + (size_t)b * strideA + (size_t)m0 * lda;
    const __nv_bfloat16* tAl = Al + (size_t)b * strideA + (size_t)m0 * lda;
    const __nv_bfloat16* pBh = Bh + (size_t)b * strideB;
    const __nv_bfloat16* pBl = Bl + (size_t)b * strideB;

    float acc[2][4][4];
    #pragma unroll
    for (int i = 0; i < 2; ++i)
        #pragma unroll
        for (int j = 0; j < 4; ++j)
            #pragma unroll
            for (int q = 0; q < 4; ++q) acc[i][j][q] = 0.0f;

    auto load_stage = [&](int c, int st) {
        const uint32_t base = sb + st * STAGE_BYTES;
        #pragma unroll
        for (int i = 0; i < 4; ++i) {
            int idx = i * 256 + tid;
            int row = idx >> 3, sl = idx & 7;
            uint32_t doff = SWZ128(row * 128 + sl * 16);
            CP_ASYNC16(base + doff,         tAh + (size_t)row * lda + c * 64 + sl * 8);
            CP_ASYNC16(base + 16384 + doff, tAl + (size_t)row * lda + c * 64 + sl * 8);
        }
        #pragma unroll
        for (int i = 0; i < 2; ++i) {
            int idx = i * 256 + tid;
            int row = idx >> 3, sl = idx & 7;
            uint32_t doff = SWZ128(row * 128 + sl * 16);
            if (B_KMAJOR) {
                CP_ASYNC16(base + 32768 + doff, pBh + (size_t)(n0 + row) * ldb + c * 64 + sl * 8);
                CP_ASYNC16(base + 40960 + doff, pBl + (size_t)(n0 + row) * ldb + c * 64 + sl * 8);
            } else {
                CP_ASYNC16(base + 32768 + doff, pBh + (size_t)(c * 64 + row) * ldb + n0 + sl * 8);
                CP_ASYNC16(base + 40960 + doff, pBl + (size_t)(c * 64 + row) * ldb + n0 + sl * 8);
            }
        }
        CP_COMMIT();
    };

    load_stage(0, 0);

    for (int c = 0; c < nk; ++c) {
        CP_WAIT0();
        __syncthreads();
        if (c + 1 < nk) load_stage(c + 1, (c + 1) & 1);

        const uint32_t base = sb + (c & 1) * STAGE_BYTES;
        const uint32_t sAh = base, sAl = base + 16384;
        const uint32_t sBh = base + 32768, sBl = base + 40960;

        #pragma unroll
        for (int ks = 0; ks < 4; ++ks) {
            // --- stage 1: hi fragments, hh product ---
            uint32_t ah[2][4], bh[4][2];
            #pragma unroll
            for (int mt = 0; mt < 2; ++mt) {
                int row = warp_m * 32 + mt * 16 + (lane & 15);
                uint32_t off = SWZ128(row * 128 + ks * 32 + ((lane >> 4) << 4));
                LDSM_X4(ah[mt][0], ah[mt][1], ah[mt][2], ah[mt][3], sAh + off);
            }
            #pragma unroll
            for (int nt2 = 0; nt2 < 2; ++nt2) {
                if (B_KMAJOR) {
                    int row = warp_n * 32 + nt2 * 16 + ((lane >> 4) << 3) + (lane & 7);
                    uint32_t off = SWZ128(row * 128 + ks * 32 + (((lane >> 3) & 1) << 4));
                    LDSM_X4(bh[2 * nt2][0], bh[2 * nt2][1], bh[2 * nt2 + 1][0], bh[2 * nt2 + 1][1], sBh + off);
                } else {
                    int krow = ks * 16 + (((lane >> 3) & 1) << 3) + (lane & 7);
                    int col  = warp_n * 32 + nt2 * 16 + ((lane >> 4) << 3);
                    uint32_t off = SWZ128(krow * 128 + col * 2);
                    LDSM_X4T(bh[2 * nt2][0], bh[2 * nt2][1], bh[2 * nt2 + 1][0], bh[2 * nt2 + 1][1], sBh + off);
                }
            }
            #pragma unroll
            for (int mt = 0; mt < 2; ++mt)
                #pragma unroll
                for (int nt = 0; nt < 4; ++nt)
                    MMA_BF16(acc[mt][nt], ah[mt][0], ah[mt][1], ah[mt][2], ah[mt][3], bh[nt][0], bh[nt][1]);

            // --- stage 2: al fragments, al*bh product ---
            uint32_t al[2][4];
            #pragma unroll
            for (int mt = 0; mt < 2; ++mt) {
                int row = warp_m * 32 + mt * 16 + (lane & 15);
                uint32_t off = SWZ128(row * 128 + ks * 32 + ((lane >> 4) << 4));
                LDSM_X4(al[mt][0], al[mt][1], al[mt][2], al[mt][3], sAl + off);
            }
            #pragma unroll
            for (int mt = 0; mt < 2; ++mt)
                #pragma unroll
                for (int nt = 0; nt < 4; ++nt)
                    MMA_BF16(acc[mt][nt], al[mt][0], al[mt][1], al[mt][2], al[mt][3], bh[nt][0], bh[nt][1]);

            // --- stage 3: bl fragments, ah*bl product ---
            uint32_t bl[4][2];
            #pragma unroll
            for (int nt2 = 0; nt2 < 2; ++nt2) {
                if (B_KMAJOR) {
                    int row = warp_n * 32 + nt2 * 16 + ((lane >> 4) << 3) + (lane & 7);
                    uint32_t off = SWZ128(row * 128 + ks * 32 + (((lane >> 3) & 1) << 4));
                    LDSM_X4(bl[2 * nt2][0], bl[2 * nt2][1], bl[2 * nt2 + 1][0], bl[2 * nt2 + 1][1], sBl + off);
                } else {
                    int krow = ks * 16 + (((lane >> 3) & 1) << 3) + (lane & 7);
                    int col  = warp_n * 32 + nt2 * 16 + ((lane >> 4) << 3);
                    uint32_t off = SWZ128(krow * 128 + col * 2);
                    LDSM_X4T(bl[2 * nt2][0], bl[2 * nt2][1], bl[2 * nt2 + 1][0], bl[2 * nt2 + 1][1], sBl + off);
                }
            }
            #pragma unroll
            for (int mt = 0; mt < 2; ++mt)
                #pragma unroll
                for (int nt = 0; nt < 4; ++nt)
                    MMA_BF16(acc[mt][nt], ah[mt][0], ah[mt][1], ah[mt][2], ah[mt][3], bl[nt][0], bl[nt][1]);
        }
    }

    // Epilogue: D is write-once (scores read once later; out never read) ->
    // evict-first streaming stores keep L2 free for reusable tiles.
    float* Db = D + (size_t)b * strideD;
    #pragma unroll
    for (int mt = 0; mt < 2; ++mt) {
        int row = m0 + warp_m * 32 + mt * 16 + (lane >> 2);
        #pragma unroll
        for (int nt = 0; nt < 4; ++nt) {
            int col = n0 + warp_n * 32 + nt * 8 + (lane & 3) * 2;
            __stcs(reinterpret_cast<float2*>(Db + (size_t)row * ldd + col),
                   make_float2(acc[mt][nt][0], acc[mt][nt][1]));
            __stcs(reinterpret_cast<float2*>(Db + (size_t)(row + 8) * ldd + col),
                   make_float2(acc[mt][nt][2], acc[mt][nt][3]));
        }
    }
}

// ---------------------------------------------------------------------------
// Softmax over compacted columns j < cnt; skips 128-col chunks >= npad.
// Scores read-once -> __ldcs. __expf: error ~1e-6 rel, invisible here.
// ---------------------------------------------------------------------------
__global__ void __launch_bounds__(256) softmax_split()
{
    const int row  = blockIdx.x * 8 + (threadIdx.x >> 5);
    const int lane = threadIdx.x & 31;
    const int b    = row >> 9;
    const int cnt  = g_cnt[b];
    const int npad = g_npad[b];

    const float* p = g_scores + (size_t)row * S_DIM;

    float4 fv[4];
    float mx = -3e38f;
    #pragma unroll
    for (int c = 0; c < 4; ++c) {
        if (c * 128 < npad) {
            const int s = c * 128 + lane * 4;
            float4 x = __ldcs(reinterpret_cast<const float4*>(p + s));
            x.x = (s + 0 < cnt) ? x.x : NEG_INF_F;
            x.y = (s + 1 < cnt) ? x.y : NEG_INF_F;
            x.z = (s + 2 < cnt) ? x.z : NEG_INF_F;
            x.w = (s + 3 < cnt) ? x.w : NEG_INF_F;
            fv[c] = x;
            mx = fmaxf(mx, fmaxf(fmaxf(x.x, x.y), fmaxf(x.z, x.w)));
        } else {
            fv[c] = make_float4(NEG_INF_F, NEG_INF_F, NEG_INF_F, NEG_INF_F);
        }
    }
    #pragma unroll
    for (int o = 16; o > 0; o >>= 1) mx = fmaxf(mx, __shfl_xor_sync(0xffffffffu, mx, o));

    float sum = 0.0f;
    #pragma unroll
    for (int c = 0; c < 4; ++c) {
        if (c * 128 < npad) {
            fv[c].x = __expf(fv[c].x - mx); fv[c].y = __expf(fv[c].y - mx);
            fv[c].z = __expf(fv[c].z - mx); fv[c].w = __expf(fv[c].w - mx);
            sum += fv[c].x + fv[c].y + fv[c].z + fv[c].w;
        }
    }
    #pragma unroll
    for (int o = 16; o > 0; o >>= 1) sum += __shfl_xor_sync(0xffffffffu, sum, o);

    const float inv = 1.0f / sum;
    #pragma unroll
    for (int c = 0; c < 4; ++c) {
        if (c * 128 < npad) {
            const int s = c * 128 + lane * 4;
            float v0 = fv[c].x * inv, v1 = fv[c].y * inv, v2 = fv[c].z * inv, v3 = fv[c].w * inv;
            __nv_bfloat16 h0, l0, h1, l1, h2, l2, h3, l3;
            split2(v0, h0, l0); split2(v1, h1, l1); split2(v2, h2, l2); split2(v3, h3, l3);
            __nv_bfloat162* ph = reinterpret_cast<__nv_bfloat162*>(g_Ph + (size_t)row * S_DIM + s);
            __nv_bfloat162* pl = reinterpret_cast<__nv_bfloat162*>(g_Pl + (size_t)row * S_DIM + s);
            ph[0] = __nv_bfloat162{h0, h1}; ph[1] = __nv_bfloat162{h2, h3};
            pl[0] = __nv_bfloat162{l0, l1}; pl[1] = __nv_bfloat162{l2, l3};
        }
    }
}

// ---------------------------------------------------------------------------
// Launch
// ---------------------------------------------------------------------------
extern "C" void kernel_launch(void* const* d_in, const int* in_sizes, int n_in,
                              void* d_out, int out_size)
{
    const float* X    = (const float*)d_in[0];   // [B, S, H]
    const int*   mask = (const int*)  d_in[1];   // [B, S]
    const float* W    = (const float*)d_in[2];   // [L, H]
    float* out = (float*)d_out;                  // [B, L, H]

    cudaFuncSetAttribute(gemm_hmma_x3<true, true, 16>,
                         cudaFuncAttributeMaxDynamicSharedMemorySize, GEMM_SMEM);
    cudaFuncSetAttribute(gemm_hmma_x3<false, false, 0>,
                         cudaFuncAttributeMaxDynamicSharedMemorySize, GEMM_SMEM);

    void *pXh, *pXl, *pWh, *pWl, *pPh, *pPl, *pSc;
    cudaGetSymbolAddress(&pXh, g_Xh); cudaGetSymbolAddress(&pXl, g_Xl);
    cudaGetSymbolAddress(&pWh, g_Wh); cudaGetSymbolAddress(&pWl, g_Wl);
    cudaGetSymbolAddress(&pPh, g_Ph); cudaGetSymbolAddress(&pPl, g_Pl);
    cudaGetSymbolAddress(&pSc, g_scores);

    compact_mask<<<B_DIM, 512>>>(mask);
    gather_convert<<<dim3(S_DIM / 8, B_DIM + 1), 256>>>(X, W);

    // GEMM1 (NT, compacted N, NK=16): scores[b,l,j] = W[l,:] . Xc[b,j,:]
    gemm_hmma_x3<true, true, 16><<<dim3(S_DIM / 64, L_DIM / 128, B_DIM), 256, GEMM_SMEM>>>(
        (const __nv_bfloat16*)pWh, (const __nv_bfloat16*)pWl,
        (const __nv_bfloat16*)pXh, (const __nv_bfloat16*)pXl,
        (float*)pSc,
        H_DIM, H_DIM, S_DIM,
        0, (size_t)S_DIM * H_DIM, (size_t)L_DIM * S_DIM);

    softmax_split<<<(B_DIM * L_DIM) / 8, 256>>>();

    // GEMM2 (NN, compacted K): out[b,l,h] = Pc[b,l,:] . Xc[b,:,h]
    gemm_hmma_x3<false, false, 0><<<dim3(H_DIM / 64, L_DIM / 128, B_DIM), 256, GEMM_SMEM>>>(
        (const __nv_bfloat16*)pPh, (const __nv_bfloat16*)pPl,
        (const __nv_bfloat16*)pXh, (const __nv_bfloat16*)pXl,
        out,
        S_DIM, H_DIM, H_DIM,
        (size_t)L_DIM * S_DIM, (size_t)S_DIM * H_DIM, (size_t)L_DIM * H_DIM);
}

// round 17
// speedup vs baseline: 1.8376x; 1.2225x over previous
#include <cuda_runtime.h>
#include <cuda_bf16.h>
#include <stdint.h>

#define B_DIM 64
#define S_DIM 512
#define H_DIM 1024
#define L_DIM 512
#define NEG_INF_F (-1e9f)
#define P_THRESH 1e-8f

// ---------------------------------------------------------------------------
// Scratch (module-load allocations, allowed)
// ---------------------------------------------------------------------------
__device__ float         g_scores[(size_t)B_DIM * L_DIM * S_DIM];
__device__ __nv_bfloat16 g_Xh[(size_t)B_DIM * S_DIM * H_DIM];      // compacted
__device__ __nv_bfloat16 g_Xl[(size_t)B_DIM * S_DIM * H_DIM];
__device__ __nv_bfloat16 g_Wh[(size_t)L_DIM * H_DIM];
__device__ __nv_bfloat16 g_Wl[(size_t)L_DIM * H_DIM];
__device__ int   g_idx[B_DIM * S_DIM];
__device__ int   g_cnt[B_DIM];
__device__ int   g_npad[B_DIM];                                   // cnt -> mult of 64
__device__ int   g_sp_cnt[B_DIM * L_DIM];                         // survivors per row
__device__ int   g_sp_idx[(size_t)B_DIM * L_DIM * S_DIM];         // original s
__device__ float g_sp_val[(size_t)B_DIM * L_DIM * S_DIM];         // prob

// ---------------------------------------------------------------------------
// Helpers
// ---------------------------------------------------------------------------
__device__ __forceinline__ uint32_t smem_u32(const void* p) {
    uint32_t a;
    asm("{ .reg .u64 t; cvta.to.shared.u64 t, %1; cvt.u32.u64 %0, t; }" : "=r"(a) : "l"(p));
    return a;
}

#define CP_ASYNC16(dst, src) \
    asm volatile("cp.async.cg.shared.global [%0], [%1], 16;" :: "r"(dst), "l"(src))
#define CP_COMMIT()  asm volatile("cp.async.commit_group;" ::: "memory")
#define CP_WAIT0()   asm volatile("cp.async.wait_group 0;" ::: "memory")

#define LDSM_X4(r0, r1, r2, r3, a) \
    asm volatile("ldmatrix.sync.aligned.m8n8.x4.shared.b16 {%0,%1,%2,%3}, [%4];" \
        : "=r"(r0), "=r"(r1), "=r"(r2), "=r"(r3) : "r"(a))

#define MMA_BF16(d, a0, a1, a2, a3, b0, b1) \
    asm volatile("mma.sync.aligned.m16n8k16.row.col.f32.bf16.bf16.f32 " \
        "{%0,%1,%2,%3},{%4,%5,%6,%7},{%8,%9},{%0,%1,%2,%3};" \
        : "+f"((d)[0]), "+f"((d)[1]), "+f"((d)[2]), "+f"((d)[3]) \
        : "r"(a0), "r"(a1), "r"(a2), "r"(a3), "r"(b0), "r"(b1))

#define SWZ128(o) ((o) ^ (((o) >> 3) & 0x70))

__device__ __forceinline__ void split2(float v, __nv_bfloat16& h, __nv_bfloat16& l) {
    h = __float2bfloat16(v);
    l = __float2bfloat16(v - __bfloat162float(h));
}

// ---------------------------------------------------------------------------
// Mask compaction: one block of 512 threads per batch.
// ---------------------------------------------------------------------------
__global__ void __launch_bounds__(512) compact_mask(const int* __restrict__ mask) {
    const int b = blockIdx.x, tid = threadIdx.x;
    const int lane = tid & 31, w = tid >> 5;
    const int m = (mask[(size_t)b * S_DIM + tid] != 0);
    const unsigned bal = __ballot_sync(0xffffffffu, m);

    __shared__ int ws[16], woff[16];
    if (lane == 0) ws[w] = __popc(bal);
    __syncthreads();
    if (tid == 0) {
        int s = 0;
        #pragma unroll
        for (int i = 0; i < 16; ++i) { woff[i] = s; s += ws[i]; }
        g_cnt[b]  = s;
        int np = ((s + 63) >> 6) << 6;
        g_npad[b] = (np < 64) ? 64 : np;
    }
    __syncthreads();
    if (m) {
        int pos = woff[w] + __popc(bal & ((1u << lane) - 1u));
        g_idx[b * S_DIM + pos] = tid;
    }
}

// ---------------------------------------------------------------------------
// Gather + split-convert X (8 rows/block), and convert W on the extra y-slice.
// ---------------------------------------------------------------------------
__global__ void __launch_bounds__(256) gather_convert(const float* __restrict__ X,
                                                      const float* __restrict__ W) {
    const int col = threadIdx.x * 4;
    if (blockIdx.y == B_DIM) {
        const int r0 = blockIdx.x * 8;
        #pragma unroll
        for (int r = 0; r < 8; ++r) {
            const size_t o = (size_t)(r0 + r) * H_DIM + col;
            float4 v = __ldcs(reinterpret_cast<const float4*>(W + o));
            __nv_bfloat16 h0, l0, h1, l1, h2, l2, h3, l3;
            split2(v.x, h0, l0); split2(v.y, h1, l1); split2(v.z, h2, l2); split2(v.w, h3, l3);
            *reinterpret_cast<__nv_bfloat162*>(g_Wh + o)     = __nv_bfloat162{h0, h1};
            *reinterpret_cast<__nv_bfloat162*>(g_Wh + o + 2) = __nv_bfloat162{h2, h3};
            *reinterpret_cast<__nv_bfloat162*>(g_Wl + o)     = __nv_bfloat162{l0, l1};
            *reinterpret_cast<__nv_bfloat162*>(g_Wl + o + 2) = __nv_bfloat162{l2, l3};
        }
        return;
    }
    const int b = blockIdx.y;
    const int j0 = blockIdx.x * 8;
    const int npad = g_npad[b];
    if (j0 >= npad) return;
    const int cnt = g_cnt[b];

    #pragma unroll
    for (int r = 0; r < 8; ++r) {
        const int j = j0 + r;
        if (j >= npad) break;
        const size_t o = ((size_t)b * S_DIM + j) * H_DIM + col;
        if (j < cnt) {
            const int s = g_idx[b * S_DIM + j];
            float4 v = __ldcs(reinterpret_cast<const float4*>(
                X + ((size_t)b * S_DIM + s) * H_DIM + col));
            __nv_bfloat16 h0, l0, h1, l1, h2, l2, h3, l3;
            split2(v.x, h0, l0); split2(v.y, h1, l1); split2(v.z, h2, l2); split2(v.w, h3, l3);
            *reinterpret_cast<__nv_bfloat162*>(g_Xh + o)     = __nv_bfloat162{h0, h1};
            *reinterpret_cast<__nv_bfloat162*>(g_Xh + o + 2) = __nv_bfloat162{h2, h3};
            *reinterpret_cast<__nv_bfloat162*>(g_Xl + o)     = __nv_bfloat162{l0, l1};
            *reinterpret_cast<__nv_bfloat162*>(g_Xl + o + 2) = __nv_bfloat162{l2, l3};
        } else {
            *reinterpret_cast<uint2*>(g_Xh + o) = make_uint2(0, 0);
            *reinterpret_cast<uint2*>(g_Xl + o) = make_uint2(0, 0);
        }
    }
}

// ---------------------------------------------------------------------------
// GEMM1: bf16x3 split via mma.sync (proven config). CTA 128x64, K-chunk 64,
// 8 warps (4M x 2N), warp 32x32, 2-stage cp.async, one barrier/chunk,
// 2 CTAs/SM, NK=16, N_LIM early-exit, streaming epilogue stores.
// ---------------------------------------------------------------------------
#define STAGE_BYTES 49152
#define GEMM_SMEM   (2 * STAGE_BYTES)

__global__ void __launch_bounds__(256, 2) gemm1_hmma_x3(float* __restrict__ D)
{
    extern __shared__ char smem[];
    const uint32_t sb = smem_u32(smem);
    const int tid = threadIdx.x;
    const int wid = tid >> 5, lane = tid & 31;
    const int warp_m = wid & 3, warp_n = wid >> 2;
    const int b  = blockIdx.z;
    const int m0 = blockIdx.y * 128;
    const int n0 = blockIdx.x * 64;

    if (n0 >= g_npad[b]) return;
    const int nk = 16;

    const __nv_bfloat16* tAh = g_Wh + (size_t)m0 * H_DIM;
    const __nv_bfloat16* tAl = g_Wl + (size_t)m0 * H_DIM;
    const __nv_bfloat16* tBh = g_Xh + (size_t)b * S_DIM * H_DIM + (size_t)n0 * H_DIM;
    const __nv_bfloat16* tBl = g_Xl + (size_t)b * S_DIM * H_DIM + (size_t)n0 * H_DIM;

    float acc[2][4][4];
    #pragma unroll
    for (int i = 0; i < 2; ++i)
        #pragma unroll
        for (int j = 0; j < 4; ++j)
            #pragma unroll
            for (int q = 0; q < 4; ++q) acc[i][j][q] = 0.0f;

    auto load_stage = [&](int c, int st) {
        const uint32_t base = sb + st * STAGE_BYTES;
        #pragma unroll
        for (int i = 0; i < 4; ++i) {
            int idx = i * 256 + tid;
            int row = idx >> 3, sl = idx & 7;
            uint32_t doff = SWZ128(row * 128 + sl * 16);
            CP_ASYNC16(base + doff,         tAh + (size_t)row * H_DIM + c * 64 + sl * 8);
            CP_ASYNC16(base + 16384 + doff, tAl + (size_t)row * H_DIM + c * 64 + sl * 8);
        }
        #pragma unroll
        for (int i = 0; i < 2; ++i) {
            int idx = i * 256 + tid;
            int row = idx >> 3, sl = idx & 7;
            uint32_t doff = SWZ128(row * 128 + sl * 16);
            CP_ASYNC16(base + 32768 + doff, tBh + (size_t)row * H_DIM + c * 64 + sl * 8);
            CP_ASYNC16(base + 40960 + doff, tBl + (size_t)row * H_DIM + c * 64 + sl * 8);
        }
        CP_COMMIT();
    };

    load_stage(0, 0);

    for (int c = 0; c < nk; ++c) {
        CP_WAIT0();
        __syncthreads();
        if (c + 1 < nk) load_stage(c + 1, (c + 1) & 1);

        const uint32_t base = sb + (c & 1) * STAGE_BYTES;
        const uint32_t sAh = base, sAl = base + 16384;
        const uint32_t sBh = base + 32768, sBl = base + 40960;

        #pragma unroll
        for (int ks = 0; ks < 4; ++ks) {
            uint32_t ah[2][4], bh[4][2];
            #pragma unroll
            for (int mt = 0; mt < 2; ++mt) {
                int row = warp_m * 32 + mt * 16 + (lane & 15);
                uint32_t off = SWZ128(row * 128 + ks * 32 + ((lane >> 4) << 4));
                LDSM_X4(ah[mt][0], ah[mt][1], ah[mt][2], ah[mt][3], sAh + off);
            }
            #pragma unroll
            for (int nt2 = 0; nt2 < 2; ++nt2) {
                int row = warp_n * 32 + nt2 * 16 + ((lane >> 4) << 3) + (lane & 7);
                uint32_t off = SWZ128(row * 128 + ks * 32 + (((lane >> 3) & 1) << 4));
                LDSM_X4(bh[2 * nt2][0], bh[2 * nt2][1], bh[2 * nt2 + 1][0], bh[2 * nt2 + 1][1], sBh + off);
            }
            #pragma unroll
            for (int mt = 0; mt < 2; ++mt)
                #pragma unroll
                for (int nt = 0; nt < 4; ++nt)
                    MMA_BF16(acc[mt][nt], ah[mt][0], ah[mt][1], ah[mt][2], ah[mt][3], bh[nt][0], bh[nt][1]);

            uint32_t al[2][4];
            #pragma unroll
            for (int mt = 0; mt < 2; ++mt) {
                int row = warp_m * 32 + mt * 16 + (lane & 15);
                uint32_t off = SWZ128(row * 128 + ks * 32 + ((lane >> 4) << 4));
                LDSM_X4(al[mt][0], al[mt][1], al[mt][2], al[mt][3], sAl + off);
            }
            #pragma unroll
            for (int mt = 0; mt < 2; ++mt)
                #pragma unroll
                for (int nt = 0; nt < 4; ++nt)
                    MMA_BF16(acc[mt][nt], al[mt][0], al[mt][1], al[mt][2], al[mt][3], bh[nt][0], bh[nt][1]);

            uint32_t bl[4][2];
            #pragma unroll
            for (int nt2 = 0; nt2 < 2; ++nt2) {
                int row = warp_n * 32 + nt2 * 16 + ((lane >> 4) << 3) + (lane & 7);
                uint32_t off = SWZ128(row * 128 + ks * 32 + (((lane >> 3) & 1) << 4));
                LDSM_X4(bl[2 * nt2][0], bl[2 * nt2][1], bl[2 * nt2 + 1][0], bl[2 * nt2 + 1][1], sBl + off);
            }
            #pragma unroll
            for (int mt = 0; mt < 2; ++mt)
                #pragma unroll
                for (int nt = 0; nt < 4; ++nt)
                    MMA_BF16(acc[mt][nt], ah[mt][0], ah[mt][1], ah[mt][2], ah[mt][3], bl[nt][0], bl[nt][1]);
        }
    }

    float* Db = D + (size_t)b * L_DIM * S_DIM;
    #pragma unroll
    for (int mt = 0; mt < 2; ++mt) {
        int row = m0 + warp_m * 32 + mt * 16 + (lane >> 2);
        #pragma unroll
        for (int nt = 0; nt < 4; ++nt) {
            int col = n0 + warp_n * 32 + nt * 8 + (lane & 3) * 2;
            __stcs(reinterpret_cast<float2*>(Db + (size_t)row * S_DIM + col),
                   make_float2(acc[mt][nt][0], acc[mt][nt][1]));
            __stcs(reinterpret_cast<float2*>(Db + (size_t)(row + 8) * S_DIM + col),
                   make_float2(acc[mt][nt][2], acc[mt][nt][3]));
        }
    }
}

// ---------------------------------------------------------------------------
// Softmax + sparse compaction. One warp per (b,l) row. Probs <= P_THRESH
// contribute < 5e-6 total mass worst-case (expected ~1e-7) -> dropped.
// Surviving (orig_s, p) pairs written via ballot compaction (order-free sum).
// ---------------------------------------------------------------------------
__global__ void __launch_bounds__(256) softmax_sparse()
{
    const int row  = blockIdx.x * 8 + (threadIdx.x >> 5);
    const int lane = threadIdx.x & 31;
    const int b    = row >> 9;
    const int cnt  = g_cnt[b];
    const int npad = g_npad[b];

    const float* p = g_scores + (size_t)row * S_DIM;

    float4 fv[4];
    float mx = -3e38f;
    #pragma unroll
    for (int c = 0; c < 4; ++c) {
        if (c * 128 < npad) {
            const int s = c * 128 + lane * 4;
            float4 x = __ldcs(reinterpret_cast<const float4*>(p + s));
            x.x = (s + 0 < cnt) ? x.x : NEG_INF_F;
            x.y = (s + 1 < cnt) ? x.y : NEG_INF_F;
            x.z = (s + 2 < cnt) ? x.z : NEG_INF_F;
            x.w = (s + 3 < cnt) ? x.w : NEG_INF_F;
            fv[c] = x;
            mx = fmaxf(mx, fmaxf(fmaxf(x.x, x.y), fmaxf(x.z, x.w)));
        } else {
            fv[c] = make_float4(NEG_INF_F, NEG_INF_F, NEG_INF_F, NEG_INF_F);
        }
    }
    #pragma unroll
    for (int o = 16; o > 0; o >>= 1) mx = fmaxf(mx, __shfl_xor_sync(0xffffffffu, mx, o));

    float sum = 0.0f;
    #pragma unroll
    for (int c = 0; c < 4; ++c) {
        if (c * 128 < npad) {
            fv[c].x = __expf(fv[c].x - mx); fv[c].y = __expf(fv[c].y - mx);
            fv[c].z = __expf(fv[c].z - mx); fv[c].w = __expf(fv[c].w - mx);
            sum += fv[c].x + fv[c].y + fv[c].z + fv[c].w;
        }
    }
    #pragma unroll
    for (int o = 16; o > 0; o >>= 1) sum += __shfl_xor_sync(0xffffffffu, sum, o);

    const float inv = 1.0f / sum;
    int base = 0;
    int*   ridx = g_sp_idx + (size_t)row * S_DIM;
    float* rval = g_sp_val + (size_t)row * S_DIM;
    const int* idxb = g_idx + b * S_DIM;

    #pragma unroll
    for (int c = 0; c < 4; ++c) {
        if (c * 128 < npad) {
            float pv[4] = { fv[c].x * inv, fv[c].y * inv, fv[c].z * inv, fv[c].w * inv };
            #pragma unroll
            for (int e = 0; e < 4; ++e) {
                const bool keep = pv[e] > P_THRESH;
                const unsigned bal = __ballot_sync(0xffffffffu, keep);
                if (keep) {
                    const int pos = base + __popc(bal & ((1u << lane) - 1u));
                    const int j = c * 128 + lane * 4 + e;
                    ridx[pos] = idxb[j];
                    rval[pos] = pv[e];
                }
                base += __popc(bal);
            }
        }
    }
    if (lane == 0) g_sp_cnt[row] = base;
}

// ---------------------------------------------------------------------------
// Sparse attend: out[b,l,:] = sum_k p_k * X[b, s_k, :]  (exact fp32).
// One block per (b,l) row; rows of a batch are grid-adjacent so X[b] (2 MB)
// stays L2-hot.
// ---------------------------------------------------------------------------
__global__ void __launch_bounds__(256) sparse_attend(const float* __restrict__ X,
                                                     float* __restrict__ out)
{
    const int row = blockIdx.x;            // b*512 + l
    const int b   = row >> 9;
    const int cnt = g_sp_cnt[row];
    const int h   = threadIdx.x * 4;

    const int*   ridx = g_sp_idx + (size_t)row * S_DIM;
    const float* rval = g_sp_val + (size_t)row * S_DIM;

    float4 acc = make_float4(0.f, 0.f, 0.f, 0.f);
    for (int k = 0; k < cnt; ++k) {
        const int   s = ridx[k];
        const float pv = rval[k];
        float4 x = *reinterpret_cast<const float4*>(
            X + ((size_t)b * S_DIM + s) * H_DIM + h);
        acc.x += pv * x.x; acc.y += pv * x.y; acc.z += pv * x.z; acc.w += pv * x.w;
    }
    __stcs(reinterpret_cast<float4*>(out + (size_t)row * H_DIM + h), acc);
}

// ---------------------------------------------------------------------------
// Launch
// ---------------------------------------------------------------------------
extern "C" void kernel_launch(void* const* d_in, const int* in_sizes, int n_in,
                              void* d_out, int out_size)
{
    const float* X    = (const float*)d_in[0];   // [B, S, H]
    const int*   mask = (const int*)  d_in[1];   // [B, S]
    const float* W    = (const float*)d_in[2];   // [L, H]
    float* out = (float*)d_out;                  // [B, L, H]

    cudaFuncSetAttribute(gemm1_hmma_x3,
                         cudaFuncAttributeMaxDynamicSharedMemorySize, GEMM_SMEM);

    void *pSc;
    cudaGetSymbolAddress(&pSc, g_scores);

    compact_mask<<<B_DIM, 512>>>(mask);
    gather_convert<<<dim3(S_DIM / 8, B_DIM + 1), 256>>>(X, W);

    // GEMM1 (NT, compacted N, NK=16): scores[b,l,j] = W[l,:] . Xc[b,j,:]
    gemm1_hmma_x3<<<dim3(S_DIM / 64, L_DIM / 128, B_DIM), 256, GEMM_SMEM>>>((float*)pSc);

    softmax_sparse<<<(B_DIM * L_DIM) / 8, 256>>>();

    sparse_attend<<<B_DIM * L_DIM, 256>>>(X, out);
}